// round 3
// baseline (speedup 1.0000x reference)
#include <cuda_runtime.h>

#define B_   4
#define N_   256
#define DM_  128
#define DE_  8
#define H_   8
#define D_   16
#define L_   2
#define BN_  (B_ * N_)
#define SCALE 0.25f   // 1/sqrt(16)

// -------------------- scratch (no allocation allowed) --------------------
__device__ float g_Q[BN_ * DM_];
__device__ float g_K[BN_ * DM_];
__device__ float g_V[BN_ * DM_];
__device__ float g_RES[BN_ * DM_];
__device__ float g_OUT[BN_ * DM_];
__device__ float g_X[BN_ * DM_];
__device__ float g_means[N_];

// -------------------- fused Q/K/V/RES projection --------------------
#define PROJ_ROWS 8
__global__ void proj_kernel(const float* __restrict__ x_in, int from_gx,
                            const float* __restrict__ Wq, const float* __restrict__ bq,
                            const float* __restrict__ Wk, const float* __restrict__ bk,
                            const float* __restrict__ Wv, const float* __restrict__ bv,
                            const float* __restrict__ Wr, const float* __restrict__ br)
{
    __shared__ float xs[PROJ_ROWS][DM_];
    const float* x = from_gx ? g_X : x_in;
    const int t = threadIdx.x;
    const int row0 = blockIdx.x * PROJ_ROWS;

    #pragma unroll
    for (int m = 0; m < PROJ_ROWS; m++)
        xs[m][t] = x[(row0 + m) * DM_ + t];
    __syncthreads();

    float aq[PROJ_ROWS], ak[PROJ_ROWS], av[PROJ_ROWS], ar[PROJ_ROWS];
    const float bqv = bq[t], bkv = bk[t], bvv = bv[t], brv = br[t];
    #pragma unroll
    for (int m = 0; m < PROJ_ROWS; m++) { aq[m] = bqv; ak[m] = bkv; av[m] = bvv; ar[m] = brv; }

    for (int c = 0; c < DM_; c++) {
        const float wq = Wq[c * DM_ + t];
        const float wk = Wk[c * DM_ + t];
        const float wv = Wv[c * DM_ + t];
        const float wr = Wr[c * DM_ + t];
        #pragma unroll
        for (int m = 0; m < PROJ_ROWS; m++) {
            const float xv = xs[m][c];
            aq[m] = fmaf(xv, wq, aq[m]);
            ak[m] = fmaf(xv, wk, ak[m]);
            av[m] = fmaf(xv, wv, av[m]);
            ar[m] = fmaf(xv, wr, ar[m]);
        }
    }
    #pragma unroll
    for (int m = 0; m < PROJ_ROWS; m++) {
        const int idx = (row0 + m) * DM_ + t;
        g_Q[idx] = aq[m]; g_K[idx] = ak[m]; g_V[idx] = av[m]; g_RES[idx] = ar[m];
    }
}

// -------------------- row means of sim for bh == 0 --------------------
// reference: means = mean(sim, -1, keepdims)[0]  -> (N,1) from batch*head 0
__global__ void means_kernel(const float* __restrict__ edges,
                             const float* __restrict__ We,
                             const float* __restrict__ be)
{
    __shared__ float qs[D_];
    __shared__ float qWe[DE_];
    __shared__ float qbe;
    __shared__ float wsum[8];
    const int i = blockIdx.x, j = threadIdx.x;

    if (j < D_) qs[j] = g_Q[i * DM_ + j];   // b=0, h=0
    __syncthreads();
    if (j < DE_) {
        float s = 0.f;
        #pragma unroll
        for (int d = 0; d < D_; d++) s = fmaf(qs[d], We[j * DM_ + d], s);
        qWe[j] = s;
    }
    if (j == DE_) {
        float s = 0.f;
        #pragma unroll
        for (int d = 0; d < D_; d++) s = fmaf(qs[d], be[d], s);
        qbe = s;
    }
    __syncthreads();

    float sim = qbe;
    const float* kp = g_K + j * DM_;   // b=0, h=0
    #pragma unroll
    for (int d = 0; d < D_; d++) sim = fmaf(qs[d], kp[d], sim);
    const float* ep = edges + ((size_t)i * N_ + j) * DE_;  // b=0
    #pragma unroll
    for (int c = 0; c < DE_; c++) sim = fmaf(ep[c], qWe[c], sim);
    sim *= SCALE;

    #pragma unroll
    for (int o = 16; o > 0; o >>= 1) sim += __shfl_down_sync(0xffffffffu, sim, o);
    if ((j & 31) == 0) wsum[j >> 5] = sim;
    __syncthreads();
    if (j == 0) {
        float s = 0.f;
        #pragma unroll
        for (int w = 0; w < 8; w++) s += wsum[w];
        g_means[i] = s * (1.0f / N_);
    }
}

// -------------------- fused attention (edges never materialized as e) --------------------
__global__ void attn_kernel(const float* __restrict__ edges,
                            const float* __restrict__ adjacency,
                            const float* __restrict__ We,
                            const float* __restrict__ be)
{
    const int i = blockIdx.x, h = blockIdx.y, b = blockIdx.z;
    const int j = threadIdx.x;
    const int lane = j & 31, warp = j >> 5;

    __shared__ float qs[D_];
    __shared__ float qWe[DE_];
    __shared__ float qbe;
    __shared__ float part[8][25];
    __shared__ float s_sh;
    __shared__ float tot[25];

    if (j < D_) qs[j] = g_Q[(b * N_ + i) * DM_ + h * D_ + j];
    __syncthreads();
    if (j < DE_) {
        float s = 0.f;
        #pragma unroll
        for (int d = 0; d < D_; d++) s = fmaf(qs[d], We[j * DM_ + h * D_ + d], s);
        qWe[j] = s;
    }
    if (j == DE_) {
        float s = 0.f;
        #pragma unroll
        for (int d = 0; d < D_; d++) s = fmaf(qs[d], be[h * D_ + d], s);
        qbe = s;
    }
    __syncthreads();

    // edge row features for (b, i, j)
    float e[DE_];
    {
        const float4* ep = (const float4*)(edges + ((size_t)(b * N_ + i) * N_ + j) * DE_);
        const float4 e0 = ep[0], e1 = ep[1];
        e[0] = e0.x; e[1] = e0.y; e[2] = e0.z; e[3] = e0.w;
        e[4] = e1.x; e[5] = e1.y; e[6] = e1.z; e[7] = e1.w;
    }
    float kv[D_];
    {
        const float4* kp = (const float4*)(g_K + (b * N_ + j) * DM_ + h * D_);
        #pragma unroll
        for (int q4 = 0; q4 < 4; q4++) {
            const float4 kk = kp[q4];
            kv[4*q4+0] = kk.x; kv[4*q4+1] = kk.y; kv[4*q4+2] = kk.z; kv[4*q4+3] = kk.w;
        }
    }

    float sim = qbe;
    #pragma unroll
    for (int d = 0; d < D_; d++) sim = fmaf(qs[d], kv[d], sim);
    #pragma unroll
    for (int c = 0; c < DE_; c++) sim = fmaf(e[c], qWe[c], sim);
    sim *= SCALE;

    const float adjv = adjacency[((size_t)b * N_ + i) * N_ + j];
    const float p = __expf(sim - g_means[i]) * adjv;

    // softmax denominator
    float ps = p;
    #pragma unroll
    for (int o = 16; o > 0; o >>= 1) ps += __shfl_down_sync(0xffffffffu, ps, o);
    if (lane == 0) part[warp][0] = ps;
    __syncthreads();
    if (j == 0) {
        float s = 0.f;
        #pragma unroll
        for (int w = 0; w < 8; w++) s += part[w][0];
        s_sh = (s == 0.f) ? 1.f : s;
    }
    __syncthreads();
    const float a = p / s_sh;

    float vv[D_];
    {
        const float4* vp = (const float4*)(g_V + (b * N_ + j) * DM_ + h * D_);
        #pragma unroll
        for (int q4 = 0; q4 < 4; q4++) {
            const float4 vk = vp[q4];
            vv[4*q4+0] = vk.x; vv[4*q4+1] = vk.y; vv[4*q4+2] = vk.z; vv[4*q4+3] = vk.w;
        }
    }

    // 25 weighted sums: a*v[0..15], a*e[0..7], a
    float cv[25];
    #pragma unroll
    for (int d = 0; d < D_; d++) cv[d] = a * vv[d];
    #pragma unroll
    for (int c = 0; c < DE_; c++) cv[D_ + c] = a * e[c];
    cv[24] = a;

    #pragma unroll
    for (int q = 0; q < 25; q++) {
        float xv = cv[q];
        #pragma unroll
        for (int o = 16; o > 0; o >>= 1) xv += __shfl_down_sync(0xffffffffu, xv, o);
        if (lane == 0) part[warp][q] = xv;
    }
    __syncthreads();
    if (j < 25) {
        float s = 0.f;
        #pragma unroll
        for (int w = 0; w < 8; w++) s += part[w][j];
        tot[j] = s;
    }
    __syncthreads();

    if (j < D_) {
        float o = tot[j] + tot[24] * be[h * D_ + j];
        #pragma unroll
        for (int c = 0; c < DE_; c++) o = fmaf(tot[16 + c], We[c * DM_ + h * D_ + j], o);
        g_OUT[(b * N_ + i) * DM_ + h * D_ + j] = o;
    }
}

// -------------------- gate + gated residual + LayerNorm + ReLU --------------------
__device__ __forceinline__ float block_reduce_128(float v, float* sh)
{
    __syncthreads();
    #pragma unroll
    for (int o = 16; o > 0; o >>= 1) v += __shfl_down_sync(0xffffffffu, v, o);
    if ((threadIdx.x & 31) == 0) sh[threadIdx.x >> 5] = v;
    __syncthreads();
    if (threadIdx.x == 0) sh[0] = sh[0] + sh[1] + sh[2] + sh[3];
    __syncthreads();
    return sh[0];
}

__global__ void epilogue_kernel(const float* __restrict__ Wg,
                                const float* __restrict__ lng,
                                const float* __restrict__ lnb,
                                float* __restrict__ x_out, int to_gx)
{
    __shared__ float sh[4];
    const int row = blockIdx.x, t = threadIdx.x;
    const float o = g_OUT[row * DM_ + t];
    const float r = g_RES[row * DM_ + t];

    const float part = o * Wg[t] + r * Wg[DM_ + t] + (o - r) * Wg[2 * DM_ + t];
    const float gdot = block_reduce_128(part, sh);
    const float g = 1.0f / (1.0f + expf(-gdot));
    const float y = o * g + r * (1.0f - g);

    const float mu = block_reduce_128(y, sh) * (1.0f / DM_);
    const float ym = y - mu;
    const float var = block_reduce_128(ym * ym, sh) * (1.0f / DM_);
    const float yn = ym * rsqrtf(var + 1e-5f) * lng[t] + lnb[t];
    const float res = fmaxf(yn, 0.0f);

    if (to_gx) g_X[row * DM_ + t] = res;
    else       x_out[row * DM_ + t] = res;
}

// -------------------- launch --------------------
extern "C" void kernel_launch(void* const* d_in, const int* in_sizes, int n_in,
                              void* d_out, int out_size)
{
    const float* nodes = (const float*)d_in[0];
    const float* edges = (const float*)d_in[1];
    const float* adj   = (const float*)d_in[2];
    const float* Wq = (const float*)d_in[3];
    const float* bq = (const float*)d_in[4];
    const float* Wk = (const float*)d_in[5];
    const float* bk = (const float*)d_in[6];
    const float* Wv = (const float*)d_in[7];
    const float* bv = (const float*)d_in[8];
    const float* We = (const float*)d_in[9];
    const float* be = (const float*)d_in[10];
    const float* Wr = (const float*)d_in[11];
    const float* br = (const float*)d_in[12];
    const float* Wg = (const float*)d_in[13];
    const float* lng = (const float*)d_in[14];
    const float* lnb = (const float*)d_in[15];
    float* out = (float*)d_out;

    for (int l = 0; l < L_; l++) {
        proj_kernel<<<BN_ / PROJ_ROWS, DM_>>>(nodes, l > 0,
            Wq + l * DM_ * DM_, bq + l * DM_,
            Wk + l * DM_ * DM_, bk + l * DM_,
            Wv + l * DM_ * DM_, bv + l * DM_,
            Wr + l * DM_ * DM_, br + l * DM_);
        means_kernel<<<N_, N_>>>(edges, We + l * DE_ * DM_, be + l * DM_);
        attn_kernel<<<dim3(N_, H_, B_), N_>>>(edges, adj, We + l * DE_ * DM_, be + l * DM_);
        epilogue_kernel<<<BN_, DM_>>>(Wg + l * 3 * DM_, lng + l * DM_, lnb + l * DM_,
                                      out, (l < L_ - 1) ? 1 : 0);
    }
}

// round 4
// speedup vs baseline: 2.0935x; 2.0935x over previous
#include <cuda_runtime.h>

#define B_   4
#define N_   256
#define DM_  128
#define DE_  8
#define H_   8
#define D_   16
#define L_   2
#define BN_  (B_ * N_)
#define SCALE 0.25f   // 1/sqrt(16)
#define TILE_I 16
#define CVS_PAD 264   // 264 % 32 == 8 -> conflict-free strided reduce

// -------------------- scratch (no allocation allowed) --------------------
__device__ float g_Q[BN_ * DM_];
__device__ float g_K[BN_ * DM_];
__device__ float g_V[BN_ * DM_];
__device__ float g_RES[BN_ * DM_];
__device__ float g_OUT[BN_ * DM_];
__device__ float g_X[BN_ * DM_];
__device__ float g_means[N_];

// -------------------- fused Q/K/V/RES projection --------------------
#define PROJ_ROWS 8
__global__ void proj_kernel(const float* __restrict__ x_in, int from_gx,
                            const float* __restrict__ Wq, const float* __restrict__ bq,
                            const float* __restrict__ Wk, const float* __restrict__ bk,
                            const float* __restrict__ Wv, const float* __restrict__ bv,
                            const float* __restrict__ Wr, const float* __restrict__ br)
{
    __shared__ float xs[PROJ_ROWS][DM_];
    const float* x = from_gx ? g_X : x_in;
    const int t = threadIdx.x;
    const int row0 = blockIdx.x * PROJ_ROWS;

    #pragma unroll
    for (int m = 0; m < PROJ_ROWS; m++)
        xs[m][t] = x[(row0 + m) * DM_ + t];
    __syncthreads();

    float aq[PROJ_ROWS], ak[PROJ_ROWS], av[PROJ_ROWS], ar[PROJ_ROWS];
    const float bqv = bq[t], bkv = bk[t], bvv = bv[t], brv = br[t];
    #pragma unroll
    for (int m = 0; m < PROJ_ROWS; m++) { aq[m] = bqv; ak[m] = bkv; av[m] = bvv; ar[m] = brv; }

    #pragma unroll 4
    for (int c = 0; c < DM_; c++) {
        const float wq = Wq[c * DM_ + t];
        const float wk = Wk[c * DM_ + t];
        const float wv = Wv[c * DM_ + t];
        const float wr = Wr[c * DM_ + t];
        #pragma unroll
        for (int m = 0; m < PROJ_ROWS; m++) {
            const float xv = xs[m][c];
            aq[m] = fmaf(xv, wq, aq[m]);
            ak[m] = fmaf(xv, wk, ak[m]);
            av[m] = fmaf(xv, wv, av[m]);
            ar[m] = fmaf(xv, wr, ar[m]);
        }
    }
    #pragma unroll
    for (int m = 0; m < PROJ_ROWS; m++) {
        const int idx = (row0 + m) * DM_ + t;
        g_Q[idx] = aq[m]; g_K[idx] = ak[m]; g_V[idx] = av[m]; g_RES[idx] = ar[m];
    }
}

// -------------------- row means of sim for bh == 0 --------------------
// reference: means = mean(sim, -1, keepdims)[0]  -> (N,1) from batch*head 0
__global__ void means_kernel(const float* __restrict__ edges,
                             const float* __restrict__ We,
                             const float* __restrict__ be)
{
    __shared__ float qs[D_];
    __shared__ float qWe[DE_];
    __shared__ float qbe;
    __shared__ float wsum[8];
    const int i = blockIdx.x, j = threadIdx.x;

    if (j < D_) qs[j] = g_Q[i * DM_ + j];   // b=0, h=0
    __syncthreads();
    if (j < DE_) {
        float s = 0.f;
        #pragma unroll
        for (int d = 0; d < D_; d++) s = fmaf(qs[d], We[j * DM_ + d], s);
        qWe[j] = s;
    }
    if (j == DE_) {
        float s = 0.f;
        #pragma unroll
        for (int d = 0; d < D_; d++) s = fmaf(qs[d], be[d], s);
        qbe = s;
    }
    __syncthreads();

    float sim = qbe;
    const float* kp = g_K + j * DM_;   // b=0, h=0
    #pragma unroll
    for (int d = 0; d < D_; d++) sim = fmaf(qs[d], kp[d], sim);
    const float* ep = edges + ((size_t)i * N_ + j) * DE_;  // b=0
    #pragma unroll
    for (int c = 0; c < DE_; c++) sim = fmaf(ep[c], qWe[c], sim);
    sim *= SCALE;

    #pragma unroll
    for (int o = 16; o > 0; o >>= 1) sim += __shfl_down_sync(0xffffffffu, sim, o);
    if ((j & 31) == 0) wsum[j >> 5] = sim;
    __syncthreads();
    if (j == 0) {
        float s = 0.f;
        #pragma unroll
        for (int w = 0; w < 8; w++) s += wsum[w];
        g_means[i] = s * (1.0f / N_);
    }
}

// -------------------- fused attention, i-tiled: kv/vv register-resident --------------------
__global__ void __launch_bounds__(N_)
attn_kernel(const float* __restrict__ edges,
            const float* __restrict__ adjacency,
            const float* __restrict__ We,
            const float* __restrict__ be)
{
    const int it = blockIdx.x, h = blockIdx.y, b = blockIdx.z;
    const int i0 = it * TILE_I;
    const int j = threadIdx.x;
    const int lane = j & 31, warp = j >> 5;

    __shared__ float qs[TILE_I][D_];
    __shared__ float qwe[TILE_I][DE_];
    __shared__ float qbe[TILE_I];
    __shared__ float mloc[TILE_I];
    __shared__ float ssum[8];
    __shared__ float cvs[25][CVS_PAD];
    __shared__ float part[25][8];
    __shared__ float tot[25];

    // load Q tile (16 rows x 16 dims) + means
    {
        const int ii = j >> 4, d = j & 15;
        qs[ii][d] = g_Q[(b * N_ + i0 + ii) * DM_ + h * D_ + d];
        if (j < TILE_I) mloc[j] = g_means[i0 + j];
    }
    __syncthreads();
    // precompute qwe[i][c] = q_i . We[c,h-slice],  qbe[i] = q_i . be[h-slice]
    if (j < TILE_I * DE_) {
        const int ii = j >> 3, c = j & 7;
        float s = 0.f;
        #pragma unroll
        for (int d = 0; d < D_; d++) s = fmaf(qs[ii][d], We[c * DM_ + h * D_ + d], s);
        qwe[ii][c] = s;
    } else if (j < TILE_I * DE_ + TILE_I) {
        const int ii = j - TILE_I * DE_;
        float s = 0.f;
        #pragma unroll
        for (int d = 0; d < D_; d++) s = fmaf(qs[ii][d], be[h * D_ + d], s);
        qbe[ii] = s;
    }
    __syncthreads();

    // thread j owns column j for the whole i-tile: K/V rows live in registers
    float kv[D_], vv[D_];
    {
        const float4* kp = (const float4*)(g_K + (b * N_ + j) * DM_ + h * D_);
        const float4* vp = (const float4*)(g_V + (b * N_ + j) * DM_ + h * D_);
        #pragma unroll
        for (int q4 = 0; q4 < 4; q4++) {
            const float4 kk = kp[q4];
            kv[4*q4+0] = kk.x; kv[4*q4+1] = kk.y; kv[4*q4+2] = kk.z; kv[4*q4+3] = kk.w;
            const float4 vk = vp[q4];
            vv[4*q4+0] = vk.x; vv[4*q4+1] = vk.y; vv[4*q4+2] = vk.z; vv[4*q4+3] = vk.w;
        }
    }

    const float4* erow = (const float4*)(edges + ((size_t)(b * N_ + i0) * N_ + j) * DE_);
    const float*  arow = adjacency + ((size_t)b * N_ + i0) * N_ + j;
    const size_t  estep = (size_t)N_ * DE_ / 4;   // float4 step per i

    for (int ii = 0; ii < TILE_I; ii++) {
        float e[DE_];
        {
            const float4 e0 = erow[ii * estep];
            const float4 e1 = erow[ii * estep + 1];
            e[0] = e0.x; e[1] = e0.y; e[2] = e0.z; e[3] = e0.w;
            e[4] = e1.x; e[5] = e1.y; e[6] = e1.z; e[7] = e1.w;
        }
        const float adjv = arow[ii * N_];

        float sim = qbe[ii];
        #pragma unroll
        for (int d = 0; d < D_; d++) sim = fmaf(qs[ii][d], kv[d], sim);
        #pragma unroll
        for (int c = 0; c < DE_; c++) sim = fmaf(e[c], qwe[ii][c], sim);
        sim *= SCALE;
        const float p = __expf(sim - mloc[ii]) * adjv;

        // softmax denominator (one warp reduce + smem combine)
        float ps = p;
        #pragma unroll
        for (int o = 16; o > 0; o >>= 1) ps += __shfl_down_sync(0xffffffffu, ps, o);
        if (lane == 0) ssum[warp] = ps;
        __syncthreads();                                   // S1
        float s = ssum[0] + ssum[1] + ssum[2] + ssum[3]
                + ssum[4] + ssum[5] + ssum[6] + ssum[7];
        if (s == 0.f) s = 1.f;
        const float a = p / s;

        // scatter 25 contributions into smem (conflict-free: fixed q, consecutive j)
        #pragma unroll
        for (int d = 0; d < D_; d++) cvs[d][j] = a * vv[d];
        #pragma unroll
        for (int c = 0; c < DE_; c++) cvs[D_ + c][j] = a * e[c];
        cvs[24][j] = a;
        __syncthreads();                                   // S2

        // 200-thread strided partial reduce (stride 8 -> distinct banks)
        if (j < 200) {
            const int q = j >> 3, r = j & 7;
            float s2 = 0.f;
            #pragma unroll
            for (int m = 0; m < 32; m++) s2 += cvs[q][r + 8 * m];
            part[q][r] = s2;
        }
        __syncthreads();                                   // S3
        if (j < 25) {
            float s3 = part[j][0] + part[j][1] + part[j][2] + part[j][3]
                     + part[j][4] + part[j][5] + part[j][6] + part[j][7];
            tot[j] = s3;
        }
        __syncthreads();                                   // S4
        if (j < D_) {
            float o = tot[j] + tot[24] * be[h * D_ + j];
            #pragma unroll
            for (int c = 0; c < DE_; c++)
                o = fmaf(tot[D_ + c], We[c * DM_ + h * D_ + j], o);
            g_OUT[(b * N_ + i0 + ii) * DM_ + h * D_ + j] = o;
        }
    }
}

// -------------------- warp-per-row gate + gated residual + LN + ReLU --------------------
__device__ __forceinline__ float warp_allreduce(float v)
{
    #pragma unroll
    for (int o = 16; o > 0; o >>= 1) v += __shfl_xor_sync(0xffffffffu, v, o);
    return v;
}

__global__ void __launch_bounds__(256)
epilogue_kernel(const float* __restrict__ Wg,
                const float* __restrict__ lng,
                const float* __restrict__ lnb,
                float* __restrict__ x_out, int to_gx)
{
    const int warp = threadIdx.x >> 5, lane = threadIdx.x & 31;
    const int row = blockIdx.x * 8 + warp;
    const int c0 = lane * 4;

    float o[4], r[4];
    {
        const float4 o4 = *(const float4*)(g_OUT + row * DM_ + c0);
        const float4 r4 = *(const float4*)(g_RES + row * DM_ + c0);
        o[0]=o4.x; o[1]=o4.y; o[2]=o4.z; o[3]=o4.w;
        r[0]=r4.x; r[1]=r4.y; r[2]=r4.z; r[3]=r4.w;
    }
    const float4 w0 = *(const float4*)(Wg + c0);
    const float4 w1 = *(const float4*)(Wg + DM_ + c0);
    const float4 w2 = *(const float4*)(Wg + 2 * DM_ + c0);
    const float wg0[4] = {w0.x, w0.y, w0.z, w0.w};
    const float wg1[4] = {w1.x, w1.y, w1.z, w1.w};
    const float wg2[4] = {w2.x, w2.y, w2.z, w2.w};

    float gpart = 0.f;
    #pragma unroll
    for (int k = 0; k < 4; k++)
        gpart += o[k] * wg0[k] + r[k] * wg1[k] + (o[k] - r[k]) * wg2[k];
    const float gdot = warp_allreduce(gpart);
    const float g = 1.0f / (1.0f + __expf(-gdot));

    float y[4], ysum = 0.f;
    #pragma unroll
    for (int k = 0; k < 4; k++) { y[k] = o[k] * g + r[k] * (1.0f - g); ysum += y[k]; }
    const float mu = warp_allreduce(ysum) * (1.0f / DM_);

    float vsum = 0.f;
    #pragma unroll
    for (int k = 0; k < 4; k++) { const float d = y[k] - mu; vsum += d * d; }
    const float rstd = rsqrtf(warp_allreduce(vsum) * (1.0f / DM_) + 1e-5f);

    const float4 g4 = *(const float4*)(lng + c0);
    const float4 b4 = *(const float4*)(lnb + c0);
    const float lg[4] = {g4.x, g4.y, g4.z, g4.w};
    const float lb[4] = {b4.x, b4.y, b4.z, b4.w};

    float4 res;
    res.x = fmaxf((y[0] - mu) * rstd * lg[0] + lb[0], 0.f);
    res.y = fmaxf((y[1] - mu) * rstd * lg[1] + lb[1], 0.f);
    res.z = fmaxf((y[2] - mu) * rstd * lg[2] + lb[2], 0.f);
    res.w = fmaxf((y[3] - mu) * rstd * lg[3] + lb[3], 0.f);

    float* dst = to_gx ? g_X : x_out;
    *(float4*)(dst + row * DM_ + c0) = res;
}

// -------------------- launch --------------------
extern "C" void kernel_launch(void* const* d_in, const int* in_sizes, int n_in,
                              void* d_out, int out_size)
{
    const float* nodes = (const float*)d_in[0];
    const float* edges = (const float*)d_in[1];
    const float* adj   = (const float*)d_in[2];
    const float* Wq = (const float*)d_in[3];
    const float* bq = (const float*)d_in[4];
    const float* Wk = (const float*)d_in[5];
    const float* bk = (const float*)d_in[6];
    const float* Wv = (const float*)d_in[7];
    const float* bv = (const float*)d_in[8];
    const float* We = (const float*)d_in[9];
    const float* be = (const float*)d_in[10];
    const float* Wr = (const float*)d_in[11];
    const float* br = (const float*)d_in[12];
    const float* Wg = (const float*)d_in[13];
    const float* lng = (const float*)d_in[14];
    const float* lnb = (const float*)d_in[15];
    float* out = (float*)d_out;

    for (int l = 0; l < L_; l++) {
        proj_kernel<<<BN_ / PROJ_ROWS, DM_>>>(nodes, l > 0,
            Wq + l * DM_ * DM_, bq + l * DM_,
            Wk + l * DM_ * DM_, bk + l * DM_,
            Wv + l * DM_ * DM_, bv + l * DM_,
            Wr + l * DM_ * DM_, br + l * DM_);
        means_kernel<<<N_, N_>>>(edges, We + l * DE_ * DM_, be + l * DM_);
        attn_kernel<<<dim3(N_ / TILE_I, H_, B_), N_>>>(edges, adj,
            We + l * DE_ * DM_, be + l * DM_);
        epilogue_kernel<<<BN_ / 8, 256>>>(Wg + l * 3 * DM_, lng + l * DM_, lnb + l * DM_,
                                          out, (l < L_ - 1) ? 1 : 0);
    }
}

// round 5
// speedup vs baseline: 2.4221x; 1.1570x over previous
#include <cuda_runtime.h>

#define B_   4
#define N_   256
#define DM_  128
#define DE_  8
#define H_   8
#define D_   16
#define L_   2
#define BN_  (B_ * N_)
#define SCALE 0.25f   // 1/sqrt(16)
#define TILE_I 16

// -------------------- scratch (no allocation allowed) --------------------
__device__ float g_Q[BN_ * DM_];
__device__ float g_K[BN_ * DM_];
__device__ float g_V[BN_ * DM_];
__device__ float g_RES[BN_ * DM_];
__device__ float g_OUT[BN_ * DM_];
__device__ float g_X[BN_ * DM_];
__device__ float g_means[N_];

// -------------------- f32x2 packed helpers (FFMA2: ptxas won't auto-fuse) ----
__device__ __forceinline__ unsigned long long pack2(float lo, float hi) {
    unsigned long long r;
    asm("mov.b64 %0, {%1, %2};" : "=l"(r) : "f"(lo), "f"(hi));
    return r;
}
__device__ __forceinline__ void fma2(unsigned long long& d,
                                     unsigned long long a, unsigned long long b) {
    asm("fma.rn.f32x2 %0, %1, %2, %0;" : "+l"(d) : "l"(a), "l"(b));
}
__device__ __forceinline__ void unpack2(unsigned long long v, float& lo, float& hi) {
    asm("mov.b64 {%0, %1}, %2;" : "=f"(lo), "=f"(hi) : "l"(v));
}

// -------------------- fused Q/K/V/RES projection (f32x2 packed rows) --------
#define PROJ_ROWS 8
__global__ void __launch_bounds__(DM_)
proj_kernel(const float* __restrict__ x_in, int from_gx,
            const float* __restrict__ Wq, const float* __restrict__ bq,
            const float* __restrict__ Wk, const float* __restrict__ bk,
            const float* __restrict__ Wv, const float* __restrict__ bv,
            const float* __restrict__ Wr, const float* __restrict__ br)
{
    __shared__ float2 xs2[PROJ_ROWS / 2][DM_];   // packed row pairs
    const float* x = from_gx ? g_X : x_in;
    const int t = threadIdx.x;
    const int row0 = blockIdx.x * PROJ_ROWS;

    // thread t holds column t of all 8 rows -> pack pairs
    {
        float xv[PROJ_ROWS];
        #pragma unroll
        for (int m = 0; m < PROJ_ROWS; m++)
            xv[m] = x[(row0 + m) * DM_ + t];
        #pragma unroll
        for (int m2 = 0; m2 < PROJ_ROWS / 2; m2++)
            xs2[m2][t] = make_float2(xv[2 * m2], xv[2 * m2 + 1]);
    }
    __syncthreads();

    unsigned long long aq[4], ak[4], av[4], ar[4];
    {
        const unsigned long long bq2 = pack2(bq[t], bq[t]);
        const unsigned long long bk2 = pack2(bk[t], bk[t]);
        const unsigned long long bv2 = pack2(bv[t], bv[t]);
        const unsigned long long br2 = pack2(br[t], br[t]);
        #pragma unroll
        for (int m = 0; m < 4; m++) { aq[m] = bq2; ak[m] = bk2; av[m] = bv2; ar[m] = br2; }
    }

    #pragma unroll 4
    for (int c = 0; c < DM_; c++) {
        const unsigned long long wq2 = pack2(Wq[c * DM_ + t], Wq[c * DM_ + t]);
        const unsigned long long wk2 = pack2(Wk[c * DM_ + t], Wk[c * DM_ + t]);
        const unsigned long long wv2 = pack2(Wv[c * DM_ + t], Wv[c * DM_ + t]);
        const unsigned long long wr2 = pack2(Wr[c * DM_ + t], Wr[c * DM_ + t]);
        #pragma unroll
        for (int m = 0; m < 4; m++) {
            const float2 xp = xs2[m][c];
            const unsigned long long x2 = pack2(xp.x, xp.y);
            fma2(aq[m], x2, wq2);
            fma2(ak[m], x2, wk2);
            fma2(av[m], x2, wv2);
            fma2(ar[m], x2, wr2);
        }
    }
    #pragma unroll
    for (int m = 0; m < 4; m++) {
        float lo, hi;
        unpack2(aq[m], lo, hi);
        g_Q[(row0 + 2*m) * DM_ + t] = lo;  g_Q[(row0 + 2*m + 1) * DM_ + t] = hi;
        unpack2(ak[m], lo, hi);
        g_K[(row0 + 2*m) * DM_ + t] = lo;  g_K[(row0 + 2*m + 1) * DM_ + t] = hi;
        unpack2(av[m], lo, hi);
        g_V[(row0 + 2*m) * DM_ + t] = lo;  g_V[(row0 + 2*m + 1) * DM_ + t] = hi;
        unpack2(ar[m], lo, hi);
        g_RES[(row0 + 2*m) * DM_ + t] = lo; g_RES[(row0 + 2*m + 1) * DM_ + t] = hi;
    }
}

// -------------------- row means of sim for bh == 0 --------------------
__global__ void means_kernel(const float* __restrict__ edges,
                             const float* __restrict__ We,
                             const float* __restrict__ be)
{
    __shared__ float qs[D_];
    __shared__ float qWe[DE_];
    __shared__ float qbe;
    __shared__ float wsum[8];
    const int i = blockIdx.x, j = threadIdx.x;

    if (j < D_) qs[j] = g_Q[i * DM_ + j];   // b=0, h=0
    __syncthreads();
    if (j < DE_) {
        float s = 0.f;
        #pragma unroll
        for (int d = 0; d < D_; d++) s = fmaf(qs[d], We[j * DM_ + d], s);
        qWe[j] = s;
    }
    if (j == DE_) {
        float s = 0.f;
        #pragma unroll
        for (int d = 0; d < D_; d++) s = fmaf(qs[d], be[d], s);
        qbe = s;
    }
    __syncthreads();

    float sim = qbe;
    const float* kp = g_K + j * DM_;   // b=0, h=0
    #pragma unroll
    for (int d = 0; d < D_; d++) sim = fmaf(qs[d], kp[d], sim);
    const float* ep = edges + ((size_t)i * N_ + j) * DE_;  // b=0
    #pragma unroll
    for (int c = 0; c < DE_; c++) sim = fmaf(ep[c], qWe[c], sim);
    sim *= SCALE;

    #pragma unroll
    for (int o = 16; o > 0; o >>= 1) sim += __shfl_down_sync(0xffffffffu, sim, o);
    if ((j & 31) == 0) wsum[j >> 5] = sim;
    __syncthreads();
    if (j == 0) {
        float s = 0.f;
        #pragma unroll
        for (int w = 0; w < 8; w++) s += wsum[w];
        g_means[i] = s * (1.0f / N_);
    }
}

// -------------------- attention: warp-per-i, sync-free mainloop --------------
__global__ void __launch_bounds__(256)
attn_kernel(const float* __restrict__ edges,
            const float* __restrict__ adjacency,
            const float* __restrict__ We,
            const float* __restrict__ be)
{
    const int it = blockIdx.x, h = blockIdx.y, b = blockIdx.z;
    const int i0 = it * TILE_I;
    const int t = threadIdx.x;
    const int lane = t & 31, warp = t >> 5;

    __shared__ float ks[D_][N_];      // transposed: consecutive lanes -> consecutive j
    __shared__ float vs[D_][N_];
    __shared__ float qs[TILE_I][D_];
    __shared__ float qwe[TILE_I][DE_];
    __shared__ float qbe[TILE_I];
    __shared__ float mloc[TILE_I];
    __shared__ float tot_s[8][25];

    // cooperative loads: thread t = column j
    {
        const float4* kp = (const float4*)(g_K + (b * N_ + t) * DM_ + h * D_);
        const float4* vp = (const float4*)(g_V + (b * N_ + t) * DM_ + h * D_);
        #pragma unroll
        for (int q4 = 0; q4 < 4; q4++) {
            const float4 kk = kp[q4];
            ks[4*q4+0][t] = kk.x; ks[4*q4+1][t] = kk.y;
            ks[4*q4+2][t] = kk.z; ks[4*q4+3][t] = kk.w;
            const float4 vk = vp[q4];
            vs[4*q4+0][t] = vk.x; vs[4*q4+1][t] = vk.y;
            vs[4*q4+2][t] = vk.z; vs[4*q4+3][t] = vk.w;
        }
        const int ii = t >> 4, d = t & 15;
        qs[ii][d] = g_Q[(b * N_ + i0 + ii) * DM_ + h * D_ + d];
        if (t < TILE_I) mloc[t] = g_means[i0 + t];
    }
    __syncthreads();
    if (t < TILE_I * DE_) {
        const int ii = t >> 3, c = t & 7;
        float s = 0.f;
        #pragma unroll
        for (int d = 0; d < D_; d++) s = fmaf(qs[ii][d], We[c * DM_ + h * D_ + d], s);
        qwe[ii][c] = s;
    } else if (t < TILE_I * DE_ + TILE_I) {
        const int ii = t - TILE_I * DE_;
        float s = 0.f;
        #pragma unroll
        for (int d = 0; d < D_; d++) s = fmaf(qs[ii][d], be[h * D_ + d], s);
        qbe[ii] = s;
    }
    __syncthreads();

    for (int ii = warp; ii < TILE_I; ii += 8) {
        const int i = i0 + ii;
        float acc[25];                 // 0..15: sum p*v, 16..23: sum p*e, 24: sum p
        #pragma unroll
        for (int q = 0; q < 25; q++) acc[q] = 0.f;

        float qv[D_], qw[DE_];
        #pragma unroll
        for (int d = 0; d < D_; d++) qv[d] = qs[ii][d];
        #pragma unroll
        for (int c = 0; c < DE_; c++) qw[c] = qwe[ii][c];
        const float qb = qbe[ii];
        const float m  = mloc[ii];

        const float4* ep = (const float4*)(edges + (size_t)(b * N_ + i) * N_ * DE_);
        const float*  ap = adjacency + ((size_t)b * N_ + i) * N_;

        #pragma unroll 2
        for (int ch = 0; ch < N_ / 32; ch++) {
            const int j = ch * 32 + lane;
            const float4 e0 = ep[2 * j];
            const float4 e1 = ep[2 * j + 1];
            const float adjv = ap[j];
            const float e[DE_] = {e0.x, e0.y, e0.z, e0.w, e1.x, e1.y, e1.z, e1.w};

            float sim = qb;
            #pragma unroll
            for (int d = 0; d < D_; d++) sim = fmaf(qv[d], ks[d][j], sim);
            #pragma unroll
            for (int c = 0; c < DE_; c++) sim = fmaf(e[c], qw[c], sim);
            const float p = __expf(sim * SCALE - m) * adjv;

            acc[24] += p;
            #pragma unroll
            for (int d = 0; d < D_; d++) acc[d] = fmaf(p, vs[d][j], acc[d]);
            #pragma unroll
            for (int c = 0; c < DE_; c++) acc[16 + c] = fmaf(p, e[c], acc[16 + c]);
        }

        // warp tree-reduce 25 values -> lane 0 -> smem (static indices only)
        #pragma unroll
        for (int q = 0; q < 25; q++) {
            float v = acc[q];
            #pragma unroll
            for (int o = 16; o > 0; o >>= 1) v += __shfl_down_sync(0xffffffffu, v, o);
            acc[q] = v;
        }
        if (lane == 0) {
            #pragma unroll
            for (int q = 0; q < 25; q++) tot_s[warp][q] = acc[q];
        }
        __syncwarp();

        if (lane < D_) {
            const float sv  = tot_s[warp][24];
            const float inv = (sv == 0.f) ? 1.f : (1.f / sv);
            float o = tot_s[warp][lane] + sv * be[h * D_ + lane];
            #pragma unroll
            for (int c = 0; c < DE_; c++)
                o = fmaf(tot_s[warp][16 + c], We[c * DM_ + h * D_ + lane], o);
            g_OUT[(b * N_ + i) * DM_ + h * D_ + lane] = o * inv;
        }
        __syncwarp();
    }
}

// -------------------- warp-per-row gate + gated residual + LN + ReLU --------
__device__ __forceinline__ float warp_allreduce(float v)
{
    #pragma unroll
    for (int o = 16; o > 0; o >>= 1) v += __shfl_xor_sync(0xffffffffu, v, o);
    return v;
}

__global__ void __launch_bounds__(256)
epilogue_kernel(const float* __restrict__ Wg,
                const float* __restrict__ lng,
                const float* __restrict__ lnb,
                float* __restrict__ x_out, int to_gx)
{
    const int warp = threadIdx.x >> 5, lane = threadIdx.x & 31;
    const int row = blockIdx.x * 8 + warp;
    const int c0 = lane * 4;

    float o[4], r[4];
    {
        const float4 o4 = *(const float4*)(g_OUT + row * DM_ + c0);
        const float4 r4 = *(const float4*)(g_RES + row * DM_ + c0);
        o[0]=o4.x; o[1]=o4.y; o[2]=o4.z; o[3]=o4.w;
        r[0]=r4.x; r[1]=r4.y; r[2]=r4.z; r[3]=r4.w;
    }
    const float4 w0 = *(const float4*)(Wg + c0);
    const float4 w1 = *(const float4*)(Wg + DM_ + c0);
    const float4 w2 = *(const float4*)(Wg + 2 * DM_ + c0);
    const float wg0[4] = {w0.x, w0.y, w0.z, w0.w};
    const float wg1[4] = {w1.x, w1.y, w1.z, w1.w};
    const float wg2[4] = {w2.x, w2.y, w2.z, w2.w};

    float gpart = 0.f;
    #pragma unroll
    for (int k = 0; k < 4; k++)
        gpart += o[k] * wg0[k] + r[k] * wg1[k] + (o[k] - r[k]) * wg2[k];
    const float gdot = warp_allreduce(gpart);
    const float g = 1.0f / (1.0f + __expf(-gdot));

    float y[4], ysum = 0.f;
    #pragma unroll
    for (int k = 0; k < 4; k++) { y[k] = o[k] * g + r[k] * (1.0f - g); ysum += y[k]; }
    const float mu = warp_allreduce(ysum) * (1.0f / DM_);

    float vsum = 0.f;
    #pragma unroll
    for (int k = 0; k < 4; k++) { const float d = y[k] - mu; vsum += d * d; }
    const float rstd = rsqrtf(warp_allreduce(vsum) * (1.0f / DM_) + 1e-5f);

    const float4 g4 = *(const float4*)(lng + c0);
    const float4 b4 = *(const float4*)(lnb + c0);
    const float lg[4] = {g4.x, g4.y, g4.z, g4.w};
    const float lb[4] = {b4.x, b4.y, b4.z, b4.w};

    float4 res;
    res.x = fmaxf((y[0] - mu) * rstd * lg[0] + lb[0], 0.f);
    res.y = fmaxf((y[1] - mu) * rstd * lg[1] + lb[1], 0.f);
    res.z = fmaxf((y[2] - mu) * rstd * lg[2] + lb[2], 0.f);
    res.w = fmaxf((y[3] - mu) * rstd * lg[3] + lb[3], 0.f);

    float* dst = to_gx ? g_X : x_out;
    *(float4*)(dst + row * DM_ + c0) = res;
}

// -------------------- launch --------------------
extern "C" void kernel_launch(void* const* d_in, const int* in_sizes, int n_in,
                              void* d_out, int out_size)
{
    const float* nodes = (const float*)d_in[0];
    const float* edges = (const float*)d_in[1];
    const float* adj   = (const float*)d_in[2];
    const float* Wq = (const float*)d_in[3];
    const float* bq = (const float*)d_in[4];
    const float* Wk = (const float*)d_in[5];
    const float* bk = (const float*)d_in[6];
    const float* Wv = (const float*)d_in[7];
    const float* bv = (const float*)d_in[8];
    const float* We = (const float*)d_in[9];
    const float* be = (const float*)d_in[10];
    const float* Wr = (const float*)d_in[11];
    const float* br = (const float*)d_in[12];
    const float* Wg = (const float*)d_in[13];
    const float* lng = (const float*)d_in[14];
    const float* lnb = (const float*)d_in[15];
    float* out = (float*)d_out;

    for (int l = 0; l < L_; l++) {
        proj_kernel<<<BN_ / PROJ_ROWS, DM_>>>(nodes, l > 0,
            Wq + l * DM_ * DM_, bq + l * DM_,
            Wk + l * DM_ * DM_, bk + l * DM_,
            Wv + l * DM_ * DM_, bv + l * DM_,
            Wr + l * DM_ * DM_, br + l * DM_);
        means_kernel<<<N_, N_>>>(edges, We + l * DE_ * DM_, be + l * DM_);
        attn_kernel<<<dim3(N_ / TILE_I, H_, B_), 256>>>(edges, adj,
            We + l * DE_ * DM_, be + l * DM_);
        epilogue_kernel<<<BN_ / 8, 256>>>(Wg + l * 3 * DM_, lng + l * DM_, lnb + l * DM_,
                                          out, (l < L_ - 1) ? 1 : 0);
    }
}

// round 7
// speedup vs baseline: 2.5173x; 1.0393x over previous
#include <cuda_runtime.h>

#define B_   4
#define N_   256
#define DM_  128
#define DE_  8
#define H_   8
#define D_   16
#define L_   2
#define BN_  (B_ * N_)
#define SCALE 0.25f   // 1/sqrt(16)
#define TILE_I 16
#define GRID 128      // < 148 SMs -> all CTAs resident even at 1 CTA/SM (no deadlock)

typedef unsigned long long ull;

// -------------------- scratch (no allocation allowed) --------------------
__device__ float g_Q[BN_ * DM_];
__device__ float g_K[BN_ * DM_];
__device__ float g_V[BN_ * DM_];
__device__ float g_RES[BN_ * DM_];
__device__ float g_OUT[BN_ * DM_];
__device__ float g_X[BN_ * DM_];
__device__ float g_means[N_];
__device__ unsigned g_bar;

// -------------------- f32x2 packed helpers --------------------
__device__ __forceinline__ ull pack2(float lo, float hi) {
    ull r;
    asm("mov.b64 %0, {%1, %2};" : "=l"(r) : "f"(lo), "f"(hi));
    return r;
}
__device__ __forceinline__ void fma2(ull& d, ull a, ull b) {
    asm("fma.rn.f32x2 %0, %1, %2, %0;" : "+l"(d) : "l"(a), "l"(b));
}
__device__ __forceinline__ void unpack2(ull v, float& lo, float& hi) {
    asm("mov.b64 {%0, %1}, %2;" : "=f"(lo), "=f"(hi) : "l"(v));
}

__device__ __forceinline__ float warp_allreduce(float v) {
    #pragma unroll
    for (int o = 16; o > 0; o >>= 1) v += __shfl_xor_sync(0xffffffffu, v, o);
    return v;
}

// -------------------- smem union across phases --------------------
struct AttnS {
    float2 ks2[D_ / 2][N_];     // 16 KB, [d-pair][j]
    float2 vs2[D_ / 2][N_];     // 16 KB
    float  qs[TILE_I][D_];
    float  qwe[TILE_I][DE_];
    float  qbe[TILE_I];
    float  mloc[TILE_I];
    float  tot[8][25];
};
struct ProjS { float xs[DM_][4]; };     // [col][row-in-group]
struct MeansS { float qs[D_]; float qwe[DE_]; float qbe; float wsum[8]; };
union SmemU { AttnS a; ProjS p; MeansS m; };

// -------------------- grid barrier (monotonic target, reset per replay) -----
__device__ __forceinline__ void grid_barrier(unsigned target) {
    __syncthreads();
    if (threadIdx.x == 0) {
        __threadfence();                          // release my block's writes
        atomicAdd(&g_bar, 1u);
        while (atomicAdd(&g_bar, 0u) < target) __nanosleep(64);
        __threadfence();                          // acquire
    }
    __syncthreads();
}

__global__ void reset_bar_kernel() { g_bar = 0u; }

// ============================================================================
__global__ void __launch_bounds__(256)
mega_kernel(const float* __restrict__ nodes,
            const float* __restrict__ edges,
            const float* __restrict__ adjacency,
            const float* __restrict__ Wq, const float* __restrict__ bq,
            const float* __restrict__ Wk, const float* __restrict__ bk,
            const float* __restrict__ Wv, const float* __restrict__ bv,
            const float* __restrict__ We, const float* __restrict__ be,
            const float* __restrict__ Wr, const float* __restrict__ br,
            const float* __restrict__ Wg,
            const float* __restrict__ lng, const float* __restrict__ lnb,
            float* __restrict__ out)
{
    __shared__ SmemU sm;
    const int t = threadIdx.x;
    const int lane = t & 31, warp = t >> 5;
    unsigned tgt = 0;

    for (int l = 0; l < L_; l++) {
        const float* lWq = Wq + l * DM_ * DM_;  const float* lbq = bq + l * DM_;
        const float* lWk = Wk + l * DM_ * DM_;  const float* lbk = bk + l * DM_;
        const float* lWv = Wv + l * DM_ * DM_;  const float* lbv = bv + l * DM_;
        const float* lWe = We + l * DE_ * DM_;  const float* lbe = be + l * DM_;
        const float* lWr = Wr + l * DM_ * DM_;  const float* lbr = br + l * DM_;
        const float* lWg = Wg + l * 3 * DM_;
        const float* llng = lng + l * DM_;      const float* llnb = lnb + l * DM_;

        // ================= phase 1: fused Q/K/V/RES projection =================
        // 8 rows per block, in 2 groups of 4 (thread: col = t&127, half = t>>7)
        for (int g = 0; g < 2; g++) {
            const int col = t & 127, half = t >> 7;     // half -> rows {2h, 2h+1}
            const int row0 = (blockIdx.x * 2 + g) * 4;
            const float* x = l ? g_X : nodes;
            sm.p.xs[col][2 * half]     = __ldcg(x + (row0 + 2 * half) * DM_ + col);
            sm.p.xs[col][2 * half + 1] = __ldcg(x + (row0 + 2 * half + 1) * DM_ + col);
            __syncthreads();

            ull aq = pack2(lbq[col], lbq[col]);
            ull ak = pack2(lbk[col], lbk[col]);
            ull av = pack2(lbv[col], lbv[col]);
            ull ar = pack2(lbr[col], lbr[col]);

            #pragma unroll 4
            for (int c = 0; c < DM_; c++) {
                const float wq = lWq[c * DM_ + col];
                const float wk = lWk[c * DM_ + col];
                const float wv = lWv[c * DM_ + col];
                const float wr = lWr[c * DM_ + col];
                const float2 xp = *(const float2*)&sm.p.xs[c][2 * half];
                const ull x2 = pack2(xp.x, xp.y);
                fma2(aq, x2, pack2(wq, wq));
                fma2(ak, x2, pack2(wk, wk));
                fma2(av, x2, pack2(wv, wv));
                fma2(ar, x2, pack2(wr, wr));
            }
            float lo, hi;
            const int r0 = (row0 + 2 * half) * DM_ + col;
            unpack2(aq, lo, hi); g_Q[r0] = lo;   g_Q[r0 + DM_] = hi;
            unpack2(ak, lo, hi); g_K[r0] = lo;   g_K[r0 + DM_] = hi;
            unpack2(av, lo, hi); g_V[r0] = lo;   g_V[r0 + DM_] = hi;
            unpack2(ar, lo, hi); g_RES[r0] = lo; g_RES[r0 + DM_] = hi;
            __syncthreads();   // protect xs before next group overwrites
        }
        tgt += GRID; grid_barrier(tgt);

        // ================= phase 2: sim row means for bh==0 (2 i's/block) =====
        for (int g = 0; g < 2; g++) {
            const int i = blockIdx.x * 2 + g;
            const int j = t;
            __syncthreads();   // protect sm.m from previous iteration's readers
            if (j < D_) sm.m.qs[j] = __ldcg(&g_Q[i * DM_ + j]);   // b=0,h=0
            __syncthreads();
            if (j < DE_) {
                float s = 0.f;
                #pragma unroll
                for (int d = 0; d < D_; d++) s = fmaf(sm.m.qs[d], lWe[j * DM_ + d], s);
                sm.m.qwe[j] = s;
            } else if (j == DE_) {
                float s = 0.f;
                #pragma unroll
                for (int d = 0; d < D_; d++) s = fmaf(sm.m.qs[d], lbe[d], s);
                sm.m.qbe = s;
            }
            __syncthreads();

            float sim = sm.m.qbe;
            const float4* kp = (const float4*)&g_K[j * DM_];     // b=0,h=0
            #pragma unroll
            for (int q4 = 0; q4 < 4; q4++) {
                const float4 kk = __ldcg(kp + q4);
                sim = fmaf(sm.m.qs[4*q4+0], kk.x, sim);
                sim = fmaf(sm.m.qs[4*q4+1], kk.y, sim);
                sim = fmaf(sm.m.qs[4*q4+2], kk.z, sim);
                sim = fmaf(sm.m.qs[4*q4+3], kk.w, sim);
            }
            const float4* epp = (const float4*)(edges + ((size_t)i * N_ + j) * DE_);
            const float4 e0 = epp[0], e1 = epp[1];
            sim = fmaf(e0.x, sm.m.qwe[0], sim);
            sim = fmaf(e0.y, sm.m.qwe[1], sim);
            sim = fmaf(e0.z, sm.m.qwe[2], sim);
            sim = fmaf(e0.w, sm.m.qwe[3], sim);
            sim = fmaf(e1.x, sm.m.qwe[4], sim);
            sim = fmaf(e1.y, sm.m.qwe[5], sim);
            sim = fmaf(e1.z, sm.m.qwe[6], sim);
            sim = fmaf(e1.w, sm.m.qwe[7], sim);
            sim *= SCALE;

            #pragma unroll
            for (int o = 16; o > 0; o >>= 1) sim += __shfl_down_sync(0xffffffffu, sim, o);
            if (lane == 0) sm.m.wsum[warp] = sim;
            __syncthreads();
            if (j == 0) {
                float s = 0.f;
                #pragma unroll
                for (int w = 0; w < 8; w++) s += sm.m.wsum[w];
                g_means[i] = s * (1.0f / N_);
            }
        }
        tgt += GRID; grid_barrier(tgt);

        // ================= phase 3: attention (4 units/block) =================
        for (int ku = 0; ku < 4; ku++) {
            const int u  = blockIdx.x * 4 + ku;
            const int it = u & 15, h = (u >> 4) & 7, b = u >> 7;
            const int i0 = it * TILE_I;
            __syncthreads();   // protect smem from previous use
            {
                const float4* kp = (const float4*)(g_K + (b * N_ + t) * DM_ + h * D_);
                const float4* vp = (const float4*)(g_V + (b * N_ + t) * DM_ + h * D_);
                #pragma unroll
                for (int q4 = 0; q4 < 4; q4++) {
                    const float4 kk = __ldcg(kp + q4);
                    sm.a.ks2[2*q4  ][t] = make_float2(kk.x, kk.y);
                    sm.a.ks2[2*q4+1][t] = make_float2(kk.z, kk.w);
                    const float4 vv = __ldcg(vp + q4);
                    sm.a.vs2[2*q4  ][t] = make_float2(vv.x, vv.y);
                    sm.a.vs2[2*q4+1][t] = make_float2(vv.z, vv.w);
                }
                const int ii = t >> 4, dd = t & 15;
                sm.a.qs[ii][dd] = __ldcg(&g_Q[(b * N_ + i0 + ii) * DM_ + h * D_ + dd]);
                if (t < TILE_I) sm.a.mloc[t] = __ldcg(&g_means[i0 + t]);
            }
            __syncthreads();
            if (t < TILE_I * DE_) {
                const int ii = t >> 3, c = t & 7;
                float s = 0.f;
                #pragma unroll
                for (int d = 0; d < D_; d++)
                    s = fmaf(sm.a.qs[ii][d], lWe[c * DM_ + h * D_ + d], s);
                sm.a.qwe[ii][c] = s;
            } else if (t < TILE_I * DE_ + TILE_I) {
                const int ii = t - TILE_I * DE_;
                float s = 0.f;
                #pragma unroll
                for (int d = 0; d < D_; d++)
                    s = fmaf(sm.a.qs[ii][d], lbe[h * D_ + d], s);
                sm.a.qbe[ii] = s;
            }
            __syncthreads();

            for (int ii = warp; ii < TILE_I; ii += 8) {
                const int i = i0 + ii;
                ull q2[8], qw2[4], av2[8], ae2[4];
                #pragma unroll
                for (int d2 = 0; d2 < 8; d2++) {
                    q2[d2]  = pack2(sm.a.qs[ii][2*d2], sm.a.qs[ii][2*d2+1]);
                    av2[d2] = pack2(0.f, 0.f);
                }
                #pragma unroll
                for (int c2 = 0; c2 < 4; c2++) {
                    qw2[c2] = pack2(sm.a.qwe[ii][2*c2], sm.a.qwe[ii][2*c2+1]);
                    ae2[c2] = pack2(0.f, 0.f);
                }
                const float qb   = sm.a.qbe[ii];
                const float mval = sm.a.mloc[ii];
                float ap = 0.f;
                const float4* ep  = (const float4*)(edges + (size_t)(b * N_ + i) * N_ * DE_);
                const float*  adp = adjacency + ((size_t)b * N_ + i) * N_;

                #pragma unroll 2
                for (int ch = 0; ch < N_ / 32; ch++) {
                    const int j = ch * 32 + lane;
                    const float4 e0 = ep[2 * j];
                    const float4 e1 = ep[2 * j + 1];
                    const float adjv = adp[j];
                    ull e2[4];
                    e2[0] = pack2(e0.x, e0.y); e2[1] = pack2(e0.z, e0.w);
                    e2[2] = pack2(e1.x, e1.y); e2[3] = pack2(e1.z, e1.w);

                    ull s2 = pack2(qb, 0.f);
                    #pragma unroll
                    for (int d2 = 0; d2 < 8; d2++) {
                        const float2 kk = sm.a.ks2[d2][j];
                        fma2(s2, q2[d2], pack2(kk.x, kk.y));
                    }
                    #pragma unroll
                    for (int c2 = 0; c2 < 4; c2++) fma2(s2, qw2[c2], e2[c2]);
                    float slo, shi; unpack2(s2, slo, shi);
                    const float p = __expf((slo + shi) * SCALE - mval) * adjv;
                    const ull pp = pack2(p, p);
                    ap += p;
                    #pragma unroll
                    for (int d2 = 0; d2 < 8; d2++) {
                        const float2 vv = sm.a.vs2[d2][j];
                        fma2(av2[d2], pp, pack2(vv.x, vv.y));
                    }
                    #pragma unroll
                    for (int c2 = 0; c2 < 4; c2++) fma2(ae2[c2], pp, e2[c2]);
                }

                float red[25];
                #pragma unroll
                for (int d2 = 0; d2 < 8; d2++) unpack2(av2[d2], red[2*d2], red[2*d2+1]);
                #pragma unroll
                for (int c2 = 0; c2 < 4; c2++) unpack2(ae2[c2], red[16+2*c2], red[17+2*c2]);
                red[24] = ap;
                #pragma unroll
                for (int q = 0; q < 25; q++) {
                    float v = red[q];
                    #pragma unroll
                    for (int o = 16; o > 0; o >>= 1) v += __shfl_down_sync(0xffffffffu, v, o);
                    red[q] = v;
                }
                if (lane == 0) {
                    #pragma unroll
                    for (int q = 0; q < 25; q++) sm.a.tot[warp][q] = red[q];
                }
                __syncwarp();
                if (lane < D_) {
                    const float sv  = sm.a.tot[warp][24];
                    const float inv = (sv == 0.f) ? 1.f : (1.f / sv);
                    float o = sm.a.tot[warp][lane] + sv * lbe[h * D_ + lane];
                    #pragma unroll
                    for (int c = 0; c < DE_; c++)
                        o = fmaf(sm.a.tot[warp][16 + c], lWe[c * DM_ + h * D_ + lane], o);
                    g_OUT[(b * N_ + i) * DM_ + h * D_ + lane] = o * inv;
                }
                __syncwarp();
            }
        }
        tgt += GRID; grid_barrier(tgt);

        // ================= phase 4: gate + gated residual + LN + ReLU =========
        // 8 warps x 1 row = 8 rows per block
        {
            const int row = blockIdx.x * 8 + warp;
            const int c0 = lane * 4;

            const float4 o4 = __ldcg((const float4*)(g_OUT + row * DM_ + c0));
            const float4 r4 = __ldcg((const float4*)(g_RES + row * DM_ + c0));
            const float o[4] = {o4.x, o4.y, o4.z, o4.w};
            const float r[4] = {r4.x, r4.y, r4.z, r4.w};

            const float4 w0 = *(const float4*)(lWg + c0);
            const float4 w1 = *(const float4*)(lWg + DM_ + c0);
            const float4 w2 = *(const float4*)(lWg + 2 * DM_ + c0);
            const float wg0[4] = {w0.x, w0.y, w0.z, w0.w};
            const float wg1[4] = {w1.x, w1.y, w1.z, w1.w};
            const float wg2[4] = {w2.x, w2.y, w2.z, w2.w};

            float gpart = 0.f;
            #pragma unroll
            for (int k = 0; k < 4; k++)
                gpart += o[k] * wg0[k] + r[k] * wg1[k] + (o[k] - r[k]) * wg2[k];
            const float gdot = warp_allreduce(gpart);
            const float g = 1.0f / (1.0f + __expf(-gdot));

            float y[4], ysum = 0.f;
            #pragma unroll
            for (int k = 0; k < 4; k++) { y[k] = o[k] * g + r[k] * (1.0f - g); ysum += y[k]; }
            const float mu = warp_allreduce(ysum) * (1.0f / DM_);

            float vsum = 0.f;
            #pragma unroll
            for (int k = 0; k < 4; k++) { const float d = y[k] - mu; vsum += d * d; }
            const float rstd = rsqrtf(warp_allreduce(vsum) * (1.0f / DM_) + 1e-5f);

            const float4 g4 = *(const float4*)(llng + c0);
            const float4 b4 = *(const float4*)(llnb + c0);
            float4 res;
            res.x = fmaxf((y[0] - mu) * rstd * g4.x + b4.x, 0.f);
            res.y = fmaxf((y[1] - mu) * rstd * g4.y + b4.y, 0.f);
            res.z = fmaxf((y[2] - mu) * rstd * g4.z + b4.z, 0.f);
            res.w = fmaxf((y[3] - mu) * rstd * g4.w + b4.w, 0.f);

            float* dst = (l < L_ - 1) ? g_X : out;
            *(float4*)(dst + row * DM_ + c0) = res;
        }
        if (l == 0) { tgt += GRID; grid_barrier(tgt); }
    }
}

// -------------------- launch --------------------
extern "C" void kernel_launch(void* const* d_in, const int* in_sizes, int n_in,
                              void* d_out, int out_size)
{
    const float* nodes = (const float*)d_in[0];
    const float* edges = (const float*)d_in[1];
    const float* adj   = (const float*)d_in[2];
    const float* Wq = (const float*)d_in[3];
    const float* bq = (const float*)d_in[4];
    const float* Wk = (const float*)d_in[5];
    const float* bk = (const float*)d_in[6];
    const float* Wv = (const float*)d_in[7];
    const float* bv = (const float*)d_in[8];
    const float* We = (const float*)d_in[9];
    const float* be = (const float*)d_in[10];
    const float* Wr = (const float*)d_in[11];
    const float* br = (const float*)d_in[12];
    const float* Wg = (const float*)d_in[13];
    const float* lng = (const float*)d_in[14];
    const float* lnb = (const float*)d_in[15];
    float* out = (float*)d_out;

    reset_bar_kernel<<<1, 1>>>();
    mega_kernel<<<GRID, 256>>>(nodes, edges, adj, Wq, bq, Wk, bk, Wv, bv,
                               We, be, Wr, br, Wg, lng, lnb, out);
}

// round 9
// speedup vs baseline: 3.3396x; 1.3267x over previous
#include <cuda_runtime.h>

#define B_   4
#define N_   256
#define DM_  128
#define DE_  8
#define H_   8
#define D_   16
#define L_   2
#define BN_  (B_ * N_)
#define SCALE 0.25f   // 1/sqrt(16)
#define GRID 128      // < 148 SMs -> all CTAs resident even at 1 CTA/SM
#define NT   512

typedef unsigned long long ull;

// -------------------- scratch (no allocation allowed) --------------------
__device__ float g_Q[BN_ * DM_];
__device__ float g_K[BN_ * DM_];
__device__ float g_V[BN_ * DM_];
__device__ float g_RES[BN_ * DM_];
__device__ float g_OUT[BN_ * DM_];
__device__ float g_X[BN_ * DM_];
__device__ float g_means[N_];
__device__ unsigned g_bar;

// -------------------- f32x2 packed helpers --------------------
__device__ __forceinline__ ull pack2(float lo, float hi) {
    ull r;
    asm("mov.b64 %0, {%1, %2};" : "=l"(r) : "f"(lo), "f"(hi));
    return r;
}
__device__ __forceinline__ void fma2(ull& d, ull a, ull b) {
    asm("fma.rn.f32x2 %0, %1, %2, %0;" : "+l"(d) : "l"(a), "l"(b));
}
__device__ __forceinline__ void unpack2(ull v, float& lo, float& hi) {
    asm("mov.b64 {%0, %1}, %2;" : "=f"(lo), "=f"(hi) : "l"(v));
}

__device__ __forceinline__ float warp_allreduce(float v) {
    #pragma unroll
    for (int o = 16; o > 0; o >>= 1) v += __shfl_xor_sync(0xffffffffu, v, o);
    return v;
}

// -------------------- smem union across phases --------------------
struct AttnS {
    float4 ks4[D_ / 4][N_];     // 16 KB  [d-quad][j]
    float4 vs4[D_ / 4][N_];     // 16 KB
    float  qs[64][D_];          // 4 KB
    float  qwe[64][DE_];        // 2 KB
    float  qbe[64];
    float  mloc[64];
    float  tot[16][25];
};
struct ProjS  { float2 xs[DM_][4]; };                 // [col][row-pair]
struct MeansS { float qs[2][D_]; float qwe[2][DE_]; float qbe[2]; float wsum[2][8]; };
union SmemU { AttnS a; ProjS p; MeansS m; };

// -------------------- grid barrier (monotonic target, reset per replay) -----
__device__ __forceinline__ void grid_barrier(unsigned target) {
    __syncthreads();
    if (threadIdx.x == 0) {
        __threadfence();
        atomicAdd(&g_bar, 1u);
        while (atomicAdd(&g_bar, 0u) < target) __nanosleep(64);
        __threadfence();
    }
    __syncthreads();
}

__global__ void reset_bar_kernel() { g_bar = 0u; }

// ============================================================================
__global__ void __launch_bounds__(NT)
mega_kernel(const float* __restrict__ nodes,
            const float* __restrict__ edges,
            const float* __restrict__ adjacency,
            const float* __restrict__ Wq, const float* __restrict__ bq,
            const float* __restrict__ Wk, const float* __restrict__ bk,
            const float* __restrict__ Wv, const float* __restrict__ bv,
            const float* __restrict__ We, const float* __restrict__ be,
            const float* __restrict__ Wr, const float* __restrict__ br,
            const float* __restrict__ Wg,
            const float* __restrict__ lng, const float* __restrict__ lnb,
            float* __restrict__ out)
{
    __shared__ SmemU sm;
    const int t = threadIdx.x;
    const int lane = t & 31, warp = t >> 5;
    unsigned tgt = 0;

    for (int l = 0; l < L_; l++) {
        const float* lWq = Wq + l * DM_ * DM_;  const float* lbq = bq + l * DM_;
        const float* lWk = Wk + l * DM_ * DM_;  const float* lbk = bk + l * DM_;
        const float* lWv = Wv + l * DM_ * DM_;  const float* lbv = bv + l * DM_;
        const float* lWe = We + l * DE_ * DM_;  const float* lbe = be + l * DM_;
        const float* lWr = Wr + l * DM_ * DM_;  const float* lbr = br + l * DM_;
        const float* lWg = Wg + l * 3 * DM_;
        const float* llng = lng + l * DM_;      const float* llnb = lnb + l * DM_;

        // ============ phase 1: fused Q/K/V/RES projection (8 rows/block) ======
        {
            const int col = t & 127, pr = t >> 7;       // pr -> rows {2pr, 2pr+1}
            const int row0 = blockIdx.x * 8;
            const int r = row0 + 2 * pr;
            const float* x = l ? g_X : nodes;
            sm.p.xs[col][pr] = make_float2(__ldcg(x + r * DM_ + col),
                                           __ldcg(x + (r + 1) * DM_ + col));
            __syncthreads();

            ull aq = pack2(lbq[col], lbq[col]);
            ull ak = pack2(lbk[col], lbk[col]);
            ull av = pack2(lbv[col], lbv[col]);
            ull ar = pack2(lbr[col], lbr[col]);

            #pragma unroll 4
            for (int c = 0; c < DM_; c++) {
                const float wq = lWq[c * DM_ + col];
                const float wk = lWk[c * DM_ + col];
                const float wv = lWv[c * DM_ + col];
                const float wr = lWr[c * DM_ + col];
                const float2 xp = sm.p.xs[c][pr];
                const ull x2 = pack2(xp.x, xp.y);
                fma2(aq, x2, pack2(wq, wq));
                fma2(ak, x2, pack2(wk, wk));
                fma2(av, x2, pack2(wv, wv));
                fma2(ar, x2, pack2(wr, wr));
            }
            float lo, hi;
            const int r0 = r * DM_ + col;
            unpack2(aq, lo, hi); g_Q[r0] = lo;   g_Q[r0 + DM_] = hi;
            unpack2(ak, lo, hi); g_K[r0] = lo;   g_K[r0 + DM_] = hi;
            unpack2(av, lo, hi); g_V[r0] = lo;   g_V[r0 + DM_] = hi;
            unpack2(ar, lo, hi); g_RES[r0] = lo; g_RES[r0 + DM_] = hi;
        }
        tgt += GRID; grid_barrier(tgt);

        // ============ phase 2: sim row means for bh==0 (2 i's/block, parallel) =
        {
            const int grp = t >> 8, j = t & 255;
            const int i = blockIdx.x * 2 + grp;
            const int gw = warp & 7;
            if (j < D_) sm.m.qs[grp][j] = __ldcg(&g_Q[i * DM_ + j]);   // b=0,h=0
            __syncthreads();
            if (j < DE_) {
                float s = 0.f;
                #pragma unroll
                for (int d = 0; d < D_; d++) s = fmaf(sm.m.qs[grp][d], lWe[j * DM_ + d], s);
                sm.m.qwe[grp][j] = s;
            } else if (j == DE_) {
                float s = 0.f;
                #pragma unroll
                for (int d = 0; d < D_; d++) s = fmaf(sm.m.qs[grp][d], lbe[d], s);
                sm.m.qbe[grp] = s;
            }
            __syncthreads();

            float sim = sm.m.qbe[grp];
            const float4* kp = (const float4*)&g_K[j * DM_];          // b=0,h=0
            #pragma unroll
            for (int q4 = 0; q4 < 4; q4++) {
                const float4 kk = __ldcg(kp + q4);
                sim = fmaf(sm.m.qs[grp][4*q4+0], kk.x, sim);
                sim = fmaf(sm.m.qs[grp][4*q4+1], kk.y, sim);
                sim = fmaf(sm.m.qs[grp][4*q4+2], kk.z, sim);
                sim = fmaf(sm.m.qs[grp][4*q4+3], kk.w, sim);
            }
            const float4* epp = (const float4*)(edges + ((size_t)i * N_ + j) * DE_);
            const float4 e0 = epp[0], e1 = epp[1];
            sim = fmaf(e0.x, sm.m.qwe[grp][0], sim);
            sim = fmaf(e0.y, sm.m.qwe[grp][1], sim);
            sim = fmaf(e0.z, sm.m.qwe[grp][2], sim);
            sim = fmaf(e0.w, sm.m.qwe[grp][3], sim);
            sim = fmaf(e1.x, sm.m.qwe[grp][4], sim);
            sim = fmaf(e1.y, sm.m.qwe[grp][5], sim);
            sim = fmaf(e1.z, sm.m.qwe[grp][6], sim);
            sim = fmaf(e1.w, sm.m.qwe[grp][7], sim);
            sim *= SCALE;

            #pragma unroll
            for (int o = 16; o > 0; o >>= 1) sim += __shfl_down_sync(0xffffffffu, sim, o);
            if (lane == 0) sm.m.wsum[grp][gw] = sim;
            __syncthreads();
            if (j == 0) {
                float s = 0.f;
                #pragma unroll
                for (int w = 0; w < 8; w++) s += sm.m.wsum[grp][w];
                g_means[i] = s * (1.0f / N_);
            }
        }
        tgt += GRID; grid_barrier(tgt);

        // ============ phase 3: attention — one (b,h) per block, 64 i rows =====
        {
            const int pairIdx = blockIdx.x >> 2;        // 0..31
            const int b = pairIdx >> 3, h = pairIdx & 7;
            const int i_base = (blockIdx.x & 3) * 64;

            // K/V tile: threads<256 load K row j, others V row j (transposed quads)
            {
                const int j = t & 255;
                if (t < 256) {
                    const float4* kp = (const float4*)(g_K + (b * N_ + j) * DM_ + h * D_);
                    #pragma unroll
                    for (int q4 = 0; q4 < 4; q4++) sm.a.ks4[q4][j] = __ldcg(kp + q4);
                } else {
                    const float4* vp = (const float4*)(g_V + (b * N_ + j) * DM_ + h * D_);
                    #pragma unroll
                    for (int q4 = 0; q4 < 4; q4++) sm.a.vs4[q4][j] = __ldcg(vp + q4);
                }
                // q tile: 64 x 16 = 1024 floats, 2 per thread
                #pragma unroll
                for (int rep = 0; rep < 2; rep++) {
                    const int idx = t + rep * NT;
                    const int ii = idx >> 4, dd = idx & 15;
                    sm.a.qs[ii][dd] =
                        __ldcg(&g_Q[(b * N_ + i_base + ii) * DM_ + h * D_ + dd]);
                }
                if (t < 64) sm.a.mloc[t] = __ldcg(&g_means[i_base + t]);
            }
            __syncthreads();
            {
                const int ii = t >> 3, c = t & 7;       // 512 = 64 x 8
                float s = 0.f;
                #pragma unroll
                for (int d = 0; d < D_; d++)
                    s = fmaf(sm.a.qs[ii][d], lWe[c * DM_ + h * D_ + d], s);
                sm.a.qwe[ii][c] = s;
                if (t < 64) {
                    float sb = 0.f;
                    #pragma unroll
                    for (int d = 0; d < D_; d++)
                        sb = fmaf(sm.a.qs[t][d], lbe[h * D_ + d], sb);
                    sm.a.qbe[t] = sb;
                }
            }
            __syncthreads();

            // each warp: 4 query rows
            for (int qi = 0; qi < 4; qi++) {
                const int ii = warp * 4 + qi;
                const int i = i_base + ii;

                ull q2[8], qw2[4], av2[8], ae2[4];
                #pragma unroll
                for (int d2 = 0; d2 < 8; d2++) {
                    q2[d2]  = pack2(sm.a.qs[ii][2*d2], sm.a.qs[ii][2*d2+1]);
                    av2[d2] = pack2(0.f, 0.f);
                }
                #pragma unroll
                for (int c2 = 0; c2 < 4; c2++) {
                    qw2[c2] = pack2(sm.a.qwe[ii][2*c2], sm.a.qwe[ii][2*c2+1]);
                    ae2[c2] = pack2(0.f, 0.f);
                }
                const float qb   = sm.a.qbe[ii];
                const float mval = sm.a.mloc[ii];
                float ap = 0.f;
                const float4* ep  = (const float4*)(edges + (size_t)(b * N_ + i) * N_ * DE_);
                const float*  adp = adjacency + ((size_t)b * N_ + i) * N_;

                // software pipeline: prefetch next edge chunk
                int j = lane;
                float4 fe0 = ep[2 * j], fe1 = ep[2 * j + 1];
                float  fad = adp[j];

                for (int ch = 0; ch < N_ / 32; ch++) {
                    float4 ne0, ne1; float nad = 0.f;
                    const int nj = j + 32;
                    if (ch < N_ / 32 - 1) {
                        ne0 = ep[2 * nj]; ne1 = ep[2 * nj + 1]; nad = adp[nj];
                    }
                    ull e2[4];
                    e2[0] = pack2(fe0.x, fe0.y); e2[1] = pack2(fe0.z, fe0.w);
                    e2[2] = pack2(fe1.x, fe1.y); e2[3] = pack2(fe1.z, fe1.w);

                    // split sim chain into two accumulators
                    ull s2a = pack2(qb, 0.f);
                    ull s2b = pack2(0.f, 0.f);
                    #pragma unroll
                    for (int d4 = 0; d4 < 4; d4++) {
                        const float4 kk = sm.a.ks4[d4][j];
                        fma2(s2a, q2[2*d4],     pack2(kk.x, kk.y));
                        fma2(s2b, q2[2*d4 + 1], pack2(kk.z, kk.w));
                    }
                    fma2(s2a, qw2[0], e2[0]); fma2(s2b, qw2[1], e2[1]);
                    fma2(s2a, qw2[2], e2[2]); fma2(s2b, qw2[3], e2[3]);
                    float alo, ahi, blo, bhi;
                    unpack2(s2a, alo, ahi); unpack2(s2b, blo, bhi);
                    const float p = __expf((alo + ahi + blo + bhi) * SCALE - mval) * fad;
                    const ull pp = pack2(p, p);
                    ap += p;
                    #pragma unroll
                    for (int d4 = 0; d4 < 4; d4++) {
                        const float4 vv = sm.a.vs4[d4][j];
                        fma2(av2[2*d4],     pp, pack2(vv.x, vv.y));
                        fma2(av2[2*d4 + 1], pp, pack2(vv.z, vv.w));
                    }
                    #pragma unroll
                    for (int c2 = 0; c2 < 4; c2++) fma2(ae2[c2], pp, e2[c2]);

                    fe0 = ne0; fe1 = ne1; fad = nad; j = nj;
                }

                float red[25];
                #pragma unroll
                for (int d2 = 0; d2 < 8; d2++) unpack2(av2[d2], red[2*d2], red[2*d2+1]);
                #pragma unroll
                for (int c2 = 0; c2 < 4; c2++) unpack2(ae2[c2], red[16+2*c2], red[17+2*c2]);
                red[24] = ap;
                #pragma unroll
                for (int q = 0; q < 25; q++) {
                    float v = red[q];
                    #pragma unroll
                    for (int o = 16; o > 0; o >>= 1) v += __shfl_down_sync(0xffffffffu, v, o);
                    red[q] = v;
                }
                if (lane == 0) {
                    #pragma unroll
                    for (int q = 0; q < 25; q++) sm.a.tot[warp][q] = red[q];
                }
                __syncwarp();
                if (lane < D_) {
                    const float sv  = sm.a.tot[warp][24];
                    const float inv = (sv == 0.f) ? 1.f : (1.f / sv);
                    float o = sm.a.tot[warp][lane] + sv * lbe[h * D_ + lane];
                    #pragma unroll
                    for (int c = 0; c < DE_; c++)
                        o = fmaf(sm.a.tot[warp][16 + c], lWe[c * DM_ + h * D_ + lane], o);
                    g_OUT[(b * N_ + i) * DM_ + h * D_ + lane] = o * inv;
                }
                __syncwarp();
            }
        }
        tgt += GRID; grid_barrier(tgt);

        // ============ phase 4: gate + gated residual + LN + ReLU ==============
        if (warp < 8) {
            const int row = blockIdx.x * 8 + warp;
            const int c0 = lane * 4;

            const float4 o4 = __ldcg((const float4*)(g_OUT + row * DM_ + c0));
            const float4 r4 = __ldcg((const float4*)(g_RES + row * DM_ + c0));
            const float o[4] = {o4.x, o4.y, o4.z, o4.w};
            const float r[4] = {r4.x, r4.y, r4.z, r4.w};

            const float4 w0 = *(const float4*)(lWg + c0);
            const float4 w1 = *(const float4*)(lWg + DM_ + c0);
            const float4 w2 = *(const float4*)(lWg + 2 * DM_ + c0);

            float gpart = o[0]*w0.x + r[0]*w1.x + (o[0]-r[0])*w2.x
                        + o[1]*w0.y + r[1]*w1.y + (o[1]-r[1])*w2.y
                        + o[2]*w0.z + r[2]*w1.z + (o[2]-r[2])*w2.z
                        + o[3]*w0.w + r[3]*w1.w + (o[3]-r[3])*w2.w;
            const float gdot = warp_allreduce(gpart);
            const float g = 1.0f / (1.0f + __expf(-gdot));

            float y[4], ysum = 0.f;
            #pragma unroll
            for (int k = 0; k < 4; k++) { y[k] = o[k] * g + r[k] * (1.0f - g); ysum += y[k]; }
            const float mu = warp_allreduce(ysum) * (1.0f / DM_);

            float vsum = 0.f;
            #pragma unroll
            for (int k = 0; k < 4; k++) { const float d = y[k] - mu; vsum += d * d; }
            const float rstd = rsqrtf(warp_allreduce(vsum) * (1.0f / DM_) + 1e-5f);

            const float4 g4 = *(const float4*)(llng + c0);
            const float4 b4 = *(const float4*)(llnb + c0);
            float4 res;
            res.x = fmaxf((y[0] - mu) * rstd * g4.x + b4.x, 0.f);
            res.y = fmaxf((y[1] - mu) * rstd * g4.y + b4.y, 0.f);
            res.z = fmaxf((y[2] - mu) * rstd * g4.z + b4.z, 0.f);
            res.w = fmaxf((y[3] - mu) * rstd * g4.w + b4.w, 0.f);

            float* dst = (l < L_ - 1) ? g_X : out;
            *(float4*)(dst + row * DM_ + c0) = res;
        }
        if (l == 0) { tgt += GRID; grid_barrier(tgt); }
    }
}

// -------------------- launch --------------------
extern "C" void kernel_launch(void* const* d_in, const int* in_sizes, int n_in,
                              void* d_out, int out_size)
{
    const float* nodes = (const float*)d_in[0];
    const float* edges = (const float*)d_in[1];
    const float* adj   = (const float*)d_in[2];
    const float* Wq = (const float*)d_in[3];
    const float* bq = (const float*)d_in[4];
    const float* Wk = (const float*)d_in[5];
    const float* bk = (const float*)d_in[6];
    const float* Wv = (const float*)d_in[7];
    const float* bv = (const float*)d_in[8];
    const float* We = (const float*)d_in[9];
    const float* be = (const float*)d_in[10];
    const float* Wr = (const float*)d_in[11];
    const float* br = (const float*)d_in[12];
    const float* Wg = (const float*)d_in[13];
    const float* lng = (const float*)d_in[14];
    const float* lnb = (const float*)d_in[15];
    float* out = (float*)d_out;

    reset_bar_kernel<<<1, 1>>>();
    mega_kernel<<<GRID, NT>>>(nodes, edges, adj, Wq, bq, Wk, bk, Wv, bv,
                              We, be, Wr, br, Wg, lng, lnb, out);
}

// round 11
// speedup vs baseline: 3.6547x; 1.0943x over previous
#include <cuda_runtime.h>

#define B_   4
#define N_   256
#define DM_  128
#define DE_  8
#define H_   8
#define D_   16
#define L_   2
#define BN_  (B_ * N_)
#define SCALE 0.25f   // 1/sqrt(16)
#define GRID 128      // < 148 SMs -> all CTAs resident even at 1 CTA/SM
#define NT   512

typedef unsigned long long ull;

// -------------------- scratch (no allocation allowed) --------------------
__device__ float g_Q[BN_ * DM_];
__device__ float g_K[BN_ * DM_];
__device__ float g_V[BN_ * DM_];
__device__ float g_RES[BN_ * DM_];
__device__ float g_OUT[BN_ * DM_];
__device__ float g_X[BN_ * DM_];
__device__ float g_means[N_];
__device__ unsigned g_bar;

// -------------------- f32x2 packed helpers --------------------
__device__ __forceinline__ ull pack2(float lo, float hi) {
    ull r;
    asm("mov.b64 %0, {%1, %2};" : "=l"(r) : "f"(lo), "f"(hi));
    return r;
}
__device__ __forceinline__ void fma2(ull& d, ull a, ull b) {
    asm("fma.rn.f32x2 %0, %1, %2, %0;" : "+l"(d) : "l"(a), "l"(b));
}
__device__ __forceinline__ void unpack2(ull v, float& lo, float& hi) {
    asm("mov.b64 {%0, %1}, %2;" : "=f"(lo), "=f"(hi) : "l"(v));
}

__device__ __forceinline__ float warp_allreduce(float v) {
    #pragma unroll
    for (int o = 16; o > 0; o >>= 1) v += __shfl_xor_sync(0xffffffffu, v, o);
    return v;
}

// -------------------- smem union across phases --------------------
struct AttnS {
    float4 ks4[D_ / 4][N_];     // 16 KB  [d-quad][j]
    float4 vs4[D_ / 4][N_];     // 16 KB
    float  qs[64][D_];          // 4 KB
    float  qwe[64][DE_];        // 2 KB
    float  qbe[64];
    float  mloc[64];
    float  tot[16][2][25];      // [warp][half][q]
};
struct ProjS  { float2 xs[DM_][4]; };                 // [col][row-pair]
struct MeansS { float qs[2][D_]; float qwe[2][DE_]; float qbe[2]; float wsum[2][8]; };
union SmemU { AttnS a; ProjS p; MeansS m; };

// ---- grid barrier: RED arrive (unused atomic result) + volatile LDG poll ----
__device__ __forceinline__ void grid_barrier(unsigned target) {
    __syncthreads();
    if (threadIdx.x == 0) {
        __threadfence();
        atomicAdd(&g_bar, 1u);                     // result unused -> RED
        const volatile unsigned* p = &g_bar;       // plain L2 load poll
        while (*p < target) __nanosleep(32);
        __threadfence();
    }
    __syncthreads();
}

__global__ void reset_bar_kernel() { g_bar = 0u; }

// ============================================================================
__global__ void __launch_bounds__(NT)
mega_kernel(const float* __restrict__ nodes,
            const float* __restrict__ edges,
            const float* __restrict__ adjacency,
            const float* __restrict__ Wq, const float* __restrict__ bq,
            const float* __restrict__ Wk, const float* __restrict__ bk,
            const float* __restrict__ Wv, const float* __restrict__ bv,
            const float* __restrict__ We, const float* __restrict__ be,
            const float* __restrict__ Wr, const float* __restrict__ br,
            const float* __restrict__ Wg,
            const float* __restrict__ lng, const float* __restrict__ lnb,
            float* __restrict__ out)
{
    __shared__ SmemU sm;
    const int t = threadIdx.x;
    const int lane = t & 31, warp = t >> 5;
    unsigned tgt = 0;

    for (int l = 0; l < L_; l++) {
        const float* lWq = Wq + l * DM_ * DM_;  const float* lbq = bq + l * DM_;
        const float* lWk = Wk + l * DM_ * DM_;  const float* lbk = bk + l * DM_;
        const float* lWv = Wv + l * DM_ * DM_;  const float* lbv = bv + l * DM_;
        const float* lWe = We + l * DE_ * DM_;  const float* lbe = be + l * DM_;
        const float* lWr = Wr + l * DM_ * DM_;  const float* lbr = br + l * DM_;
        const float* lWg = Wg + l * 3 * DM_;
        const float* llng = lng + l * DM_;      const float* llnb = lnb + l * DM_;

        // ============ phase 1: fused Q/K/V/RES projection (8 rows/block) ======
        {
            const int col = t & 127, pr = t >> 7;       // pr -> rows {2pr, 2pr+1}
            const int row0 = blockIdx.x * 8;
            const int r = row0 + 2 * pr;
            const float* x = l ? g_X : nodes;
            sm.p.xs[col][pr] = make_float2(__ldcg(x + r * DM_ + col),
                                           __ldcg(x + (r + 1) * DM_ + col));
            __syncthreads();

            ull aq = pack2(lbq[col], lbq[col]);
            ull ak = pack2(lbk[col], lbk[col]);
            ull av = pack2(lbv[col], lbv[col]);
            ull ar = pack2(lbr[col], lbr[col]);

            #pragma unroll 4
            for (int c = 0; c < DM_; c++) {
                const float wq = lWq[c * DM_ + col];
                const float wk = lWk[c * DM_ + col];
                const float wv = lWv[c * DM_ + col];
                const float wr = lWr[c * DM_ + col];
                const float2 xp = sm.p.xs[c][pr];
                const ull x2 = pack2(xp.x, xp.y);
                fma2(aq, x2, pack2(wq, wq));
                fma2(ak, x2, pack2(wk, wk));
                fma2(av, x2, pack2(wv, wv));
                fma2(ar, x2, pack2(wr, wr));
            }
            float lo, hi;
            const int r0 = r * DM_ + col;
            unpack2(aq, lo, hi); g_Q[r0] = lo;   g_Q[r0 + DM_] = hi;
            unpack2(ak, lo, hi); g_K[r0] = lo;   g_K[r0 + DM_] = hi;
            unpack2(av, lo, hi); g_V[r0] = lo;   g_V[r0 + DM_] = hi;
            unpack2(ar, lo, hi); g_RES[r0] = lo; g_RES[r0 + DM_] = hi;
        }
        tgt += GRID; grid_barrier(tgt);

        // ============ phase 2: sim row means for bh==0 (2 i's/block) ==========
        {
            const int grp = t >> 8, j = t & 255;
            const int i = blockIdx.x * 2 + grp;
            const int gw = warp & 7;
            if (j < D_) sm.m.qs[grp][j] = __ldcg(&g_Q[i * DM_ + j]);   // b=0,h=0
            __syncthreads();
            if (j < DE_) {
                float s = 0.f;
                #pragma unroll
                for (int d = 0; d < D_; d++) s = fmaf(sm.m.qs[grp][d], lWe[j * DM_ + d], s);
                sm.m.qwe[grp][j] = s;
            } else if (j == DE_) {
                float s = 0.f;
                #pragma unroll
                for (int d = 0; d < D_; d++) s = fmaf(sm.m.qs[grp][d], lbe[d], s);
                sm.m.qbe[grp] = s;
            }
            __syncthreads();

            float sim = sm.m.qbe[grp];
            const float4* kp = (const float4*)&g_K[j * DM_];          // b=0,h=0
            #pragma unroll
            for (int q4 = 0; q4 < 4; q4++) {
                const float4 kk = __ldcg(kp + q4);
                sim = fmaf(sm.m.qs[grp][4*q4+0], kk.x, sim);
                sim = fmaf(sm.m.qs[grp][4*q4+1], kk.y, sim);
                sim = fmaf(sm.m.qs[grp][4*q4+2], kk.z, sim);
                sim = fmaf(sm.m.qs[grp][4*q4+3], kk.w, sim);
            }
            const float4* epp = (const float4*)(edges + ((size_t)i * N_ + j) * DE_);
            const float4 e0 = epp[0], e1 = epp[1];
            sim = fmaf(e0.x, sm.m.qwe[grp][0], sim);
            sim = fmaf(e0.y, sm.m.qwe[grp][1], sim);
            sim = fmaf(e0.z, sm.m.qwe[grp][2], sim);
            sim = fmaf(e0.w, sm.m.qwe[grp][3], sim);
            sim = fmaf(e1.x, sm.m.qwe[grp][4], sim);
            sim = fmaf(e1.y, sm.m.qwe[grp][5], sim);
            sim = fmaf(e1.z, sm.m.qwe[grp][6], sim);
            sim = fmaf(e1.w, sm.m.qwe[grp][7], sim);
            sim *= SCALE;

            #pragma unroll
            for (int o = 16; o > 0; o >>= 1) sim += __shfl_down_sync(0xffffffffu, sim, o);
            if (lane == 0) sm.m.wsum[grp][gw] = sim;
            __syncthreads();
            if (j == 0) {
                float s = 0.f;
                #pragma unroll
                for (int w = 0; w < 8; w++) s += sm.m.wsum[grp][w];
                g_means[i] = s * (1.0f / N_);
            }
        }
        tgt += GRID; grid_barrier(tgt);

        // ============ phase 3: attention — (b,h) per block, half-warp pairs ====
        {
            const int pairIdx = blockIdx.x >> 2;        // 0..31
            const int b = pairIdx >> 3, h = pairIdx & 7;
            const int i_base = (blockIdx.x & 3) * 64;
            const int hf = lane >> 4;                   // half-warp id
            const int sl = lane & 15;                   // sub-lane

            // K/V tile + q tile loads
            {
                const int j = t & 255;
                if (t < 256) {
                    const float4* kp = (const float4*)(g_K + (b * N_ + j) * DM_ + h * D_);
                    #pragma unroll
                    for (int q4 = 0; q4 < 4; q4++) sm.a.ks4[q4][j] = __ldcg(kp + q4);
                } else {
                    const float4* vp = (const float4*)(g_V + (b * N_ + j) * DM_ + h * D_);
                    #pragma unroll
                    for (int q4 = 0; q4 < 4; q4++) sm.a.vs4[q4][j] = __ldcg(vp + q4);
                }
                #pragma unroll
                for (int rep = 0; rep < 2; rep++) {
                    const int idx = t + rep * NT;
                    const int ii = idx >> 4, dd = idx & 15;
                    sm.a.qs[ii][dd] =
                        __ldcg(&g_Q[(b * N_ + i_base + ii) * DM_ + h * D_ + dd]);
                }
                if (t < 64) sm.a.mloc[t] = __ldcg(&g_means[i_base + t]);
            }
            __syncthreads();
            {
                const int ii = t >> 3, c = t & 7;       // 512 = 64 x 8
                float s = 0.f;
                #pragma unroll
                for (int d = 0; d < D_; d++)
                    s = fmaf(sm.a.qs[ii][d], lWe[c * DM_ + h * D_ + d], s);
                sm.a.qwe[ii][c] = s;
                if (t < 64) {
                    float sb = 0.f;
                    #pragma unroll
                    for (int d = 0; d < D_; d++)
                        sb = fmaf(sm.a.qs[t][d], lbe[h * D_ + d], sb);
                    sm.a.qbe[t] = sb;
                }
            }
            __syncthreads();

            // each warp: 4 rows as 2 half-warp pairs
            for (int pr = 0; pr < 2; pr++) {
                const int ii = warp * 4 + pr * 2 + hf;  // this half-warp's row
                const int i  = i_base + ii;

                ull q2[8], qw2[4], av2[8], ae2[4];
                #pragma unroll
                for (int d2 = 0; d2 < 8; d2++) {
                    q2[d2]  = pack2(sm.a.qs[ii][2*d2], sm.a.qs[ii][2*d2+1]);
                    av2[d2] = pack2(0.f, 0.f);
                }
                #pragma unroll
                for (int c2 = 0; c2 < 4; c2++) {
                    qw2[c2] = pack2(sm.a.qwe[ii][2*c2], sm.a.qwe[ii][2*c2+1]);
                    ae2[c2] = pack2(0.f, 0.f);
                }
                const float qb   = sm.a.qbe[ii];
                const float mval = sm.a.mloc[ii];
                float ap = 0.f;
                const float4* ep  = (const float4*)(edges + (size_t)(b * N_ + i) * N_ * DE_);
                const float*  adp = adjacency + ((size_t)b * N_ + i) * N_;

                // software pipeline: prefetch next edge chunk (16 j per chunk)
                int j = sl;
                float4 fe0 = ep[2 * j], fe1 = ep[2 * j + 1];
                float  fad = adp[j];

                for (int ch = 0; ch < N_ / 16; ch++) {
                    float4 ne0, ne1; float nad = 0.f;
                    const int nj = j + 16;
                    if (ch < N_ / 16 - 1) {
                        ne0 = ep[2 * nj]; ne1 = ep[2 * nj + 1]; nad = adp[nj];
                    }
                    ull e2[4];
                    e2[0] = pack2(fe0.x, fe0.y); e2[1] = pack2(fe0.z, fe0.w);
                    e2[2] = pack2(fe1.x, fe1.y); e2[3] = pack2(fe1.z, fe1.w);

                    // both halves read the SAME j -> smem broadcast dedup
                    ull s2a = pack2(qb, 0.f);
                    ull s2b = pack2(0.f, 0.f);
                    #pragma unroll
                    for (int d4 = 0; d4 < 4; d4++) {
                        const float4 kk = sm.a.ks4[d4][j];
                        fma2(s2a, q2[2*d4],     pack2(kk.x, kk.y));
                        fma2(s2b, q2[2*d4 + 1], pack2(kk.z, kk.w));
                    }
                    fma2(s2a, qw2[0], e2[0]); fma2(s2b, qw2[1], e2[1]);
                    fma2(s2a, qw2[2], e2[2]); fma2(s2b, qw2[3], e2[3]);
                    float alo, ahi, blo, bhi;
                    unpack2(s2a, alo, ahi); unpack2(s2b, blo, bhi);
                    const float p = __expf((alo + ahi + blo + bhi) * SCALE - mval) * fad;
                    const ull pp = pack2(p, p);
                    ap += p;
                    #pragma unroll
                    for (int d4 = 0; d4 < 4; d4++) {
                        const float4 vv = sm.a.vs4[d4][j];
                        fma2(av2[2*d4],     pp, pack2(vv.x, vv.y));
                        fma2(av2[2*d4 + 1], pp, pack2(vv.z, vv.w));
                    }
                    #pragma unroll
                    for (int c2 = 0; c2 < 4; c2++) fma2(ae2[c2], pp, e2[c2]);

                    fe0 = ne0; fe1 = ne1; fad = nad; j = nj;
                }

                float red[25];
                #pragma unroll
                for (int d2 = 0; d2 < 8; d2++) unpack2(av2[d2], red[2*d2], red[2*d2+1]);
                #pragma unroll
                for (int c2 = 0; c2 < 4; c2++) unpack2(ae2[c2], red[16+2*c2], red[17+2*c2]);
                red[24] = ap;
                // half-warp tree: offsets 8,4,2,1; results valid at lanes 0 and 16
                #pragma unroll
                for (int q = 0; q < 25; q++) {
                    float v = red[q];
                    #pragma unroll
                    for (int o = 8; o > 0; o >>= 1) v += __shfl_down_sync(0xffffffffu, v, o);
                    red[q] = v;
                }
                if (sl == 0) {
                    #pragma unroll
                    for (int q = 0; q < 25; q++) sm.a.tot[warp][hf][q] = red[q];
                }
                __syncwarp();
                {
                    // all 32 lanes: half hf outputs its row, dims sl (0..15)
                    const float sv  = sm.a.tot[warp][hf][24];
                    const float inv = (sv == 0.f) ? 1.f : (1.f / sv);
                    float o = sm.a.tot[warp][hf][sl] + sv * lbe[h * D_ + sl];
                    #pragma unroll
                    for (int c = 0; c < DE_; c++)
                        o = fmaf(sm.a.tot[warp][hf][16 + c], lWe[c * DM_ + h * D_ + sl], o);
                    g_OUT[(b * N_ + i) * DM_ + h * D_ + sl] = o * inv;
                }
                __syncwarp();
            }
        }
        tgt += GRID; grid_barrier(tgt);

        // ============ phase 4: gate + gated residual + LN + ReLU ==============
        if (warp < 8) {
            const int row = blockIdx.x * 8 + warp;
            const int c0 = lane * 4;

            const float4 o4 = __ldcg((const float4*)(g_OUT + row * DM_ + c0));
            const float4 r4 = __ldcg((const float4*)(g_RES + row * DM_ + c0));
            const float o[4] = {o4.x, o4.y, o4.z, o4.w};
            const float r[4] = {r4.x, r4.y, r4.z, r4.w};

            const float4 w0 = *(const float4*)(lWg + c0);
            const float4 w1 = *(const float4*)(lWg + DM_ + c0);
            const float4 w2 = *(const float4*)(lWg + 2 * DM_ + c0);

            float gpart = o[0]*w0.x + r[0]*w1.x + (o[0]-r[0])*w2.x
                        + o[1]*w0.y + r[1]*w1.y + (o[1]-r[1])*w2.y
                        + o[2]*w0.z + r[2]*w1.z + (o[2]-r[2])*w2.z
                        + o[3]*w0.w + r[3]*w1.w + (o[3]-r[3])*w2.w;
            const float gdot = warp_allreduce(gpart);
            const float g = 1.0f / (1.0f + __expf(-gdot));

            float y[4], ysum = 0.f;
            #pragma unroll
            for (int k = 0; k < 4; k++) { y[k] = o[k] * g + r[k] * (1.0f - g); ysum += y[k]; }
            const float mu = warp_allreduce(ysum) * (1.0f / DM_);

            float vsum = 0.f;
            #pragma unroll
            for (int k = 0; k < 4; k++) { const float d = y[k] - mu; vsum += d * d; }
            const float rstd = rsqrtf(warp_allreduce(vsum) * (1.0f / DM_) + 1e-5f);

            const float4 g4 = *(const float4*)(llng + c0);
            const float4 b4 = *(const float4*)(llnb + c0);
            float4 res;
            res.x = fmaxf((y[0] - mu) * rstd * g4.x + b4.x, 0.f);
            res.y = fmaxf((y[1] - mu) * rstd * g4.y + b4.y, 0.f);
            res.z = fmaxf((y[2] - mu) * rstd * g4.z + b4.z, 0.f);
            res.w = fmaxf((y[3] - mu) * rstd * g4.w + b4.w, 0.f);

            float* dst = (l < L_ - 1) ? g_X : out;
            *(float4*)(dst + row * DM_ + c0) = res;
        }
        if (l == 0) { tgt += GRID; grid_barrier(tgt); }
    }
}

// -------------------- launch --------------------
extern "C" void kernel_launch(void* const* d_in, const int* in_sizes, int n_in,
                              void* d_out, int out_size)
{
    const float* nodes = (const float*)d_in[0];
    const float* edges = (const float*)d_in[1];
    const float* adj   = (const float*)d_in[2];
    const float* Wq = (const float*)d_in[3];
    const float* bq = (const float*)d_in[4];
    const float* Wk = (const float*)d_in[5];
    const float* bk = (const float*)d_in[6];
    const float* Wv = (const float*)d_in[7];
    const float* bv = (const float*)d_in[8];
    const float* We = (const float*)d_in[9];
    const float* be = (const float*)d_in[10];
    const float* Wr = (const float*)d_in[11];
    const float* br = (const float*)d_in[12];
    const float* Wg = (const float*)d_in[13];
    const float* lng = (const float*)d_in[14];
    const float* lnb = (const float*)d_in[15];
    float* out = (float*)d_out;

    reset_bar_kernel<<<1, 1>>>();
    mega_kernel<<<GRID, NT>>>(nodes, edges, adj, Wq, bq, Wk, bk, Wv, bv,
                              We, be, Wr, br, Wg, lng, lnb, out);
}